// round 15
// baseline (speedup 1.0000x reference)
#include <cuda_runtime.h>
#include <cuda_fp16.h>
#include <math.h>
#include <stdint.h>

// ---------------- problem constants (fixed shapes) ----------------
#define NTOK   3136       // 56*56
#define HH     56
#define CDIM   512
#define C3     1536
#define NHEAD  8
#define CH     64
#define HID    2048
#define BMAX   16
#define NCHUNK 7          // kv token chunks (7*448 = 3136)
#define KSCH   32         // kstats chunks (32*98 = 3136)

// packed conv weights: [0,576) w3 pairs, [576,2976) w5, [2976,7680) w7
#define WPK_W5 576
#define WPK_W7 2976
#define WPK_TOT 7680
#define WPK_CPE (WPK_TOT + 9 * 512)   // + cpe transpose

// ---------------- scratch (device globals; no allocations) --------
__device__ __half  g_x0  [(size_t)BMAX * NTOK * CDIM];
__device__ __half  g_x1  [(size_t)BMAX * NTOK * CDIM];
__device__ __half  g_hA  [(size_t)BMAX * NTOK * CDIM];
__device__ __half  g_hqkv[(size_t)BMAX * NTOK * C3];
__device__ __half  g_hH  [(size_t)BMAX * NTOK * HID];
__device__ __half  g_hw  [1536*512 + 512*512 + 2048*512 + 512*2048];
__device__ __half  g_kvT [BMAX * NHEAD * CH * CH];
__device__ __half2 g_wpk [WPK_TOT];
__device__ float   g_cwT [9 * 512];
__device__ float   g_kvpart[NCHUNK * BMAX * NHEAD * CH * CH];
__device__ float   g_kmax[BMAX * CDIM];
__device__ float   g_kscale[BMAX * CDIM];
__device__ float   g_pmax[KSCH * BMAX * CDIM];
__device__ float   g_psum[KSCH * BMAX * CDIM];

#define OFF_QKV  0
#define OFF_PROJ (1536*512)
#define OFF_FC1  (1536*512 + 512*512)
#define OFF_FC2  (1536*512 + 512*512 + 2048*512)

// ---------------- smem helpers -------------------------------------
__device__ __forceinline__ uint32_t smem_u32(const void* p) {
    uint32_t a;
    asm("{ .reg .u64 t; cvta.to.shared.u64 t, %1; cvt.u32.u64 %0, t; }" : "=r"(a) : "l"(p));
    return a;
}
__device__ __forceinline__ uint32_t swz(uint32_t r, uint32_t wp) {
    uint32_t off = r * 64 + wp * 4;
    return off ^ ((off >> 3) & 0x30);
}
__device__ __forceinline__ uint32_t swz128(uint32_t r, uint32_t ch) {
    return (r * 128 + ch * 16) ^ ((r & 7) << 4);
}
__device__ __forceinline__ void cpa16(uint32_t dst, const void* src) {
    asm volatile("cp.async.cg.shared.global [%0], [%1], 16;" :: "r"(dst), "l"(src));
}
#define CP_COMMIT() asm volatile("cp.async.commit_group;" ::: "memory")
#define CP_WAIT1()  asm volatile("cp.async.wait_group 1;" ::: "memory")
#define CP_WAIT0()  asm volatile("cp.async.wait_group 0;" ::: "memory")

__device__ __forceinline__ void ldsm_x4(uint32_t* r, uint32_t addr) {
    asm volatile("ldmatrix.sync.aligned.m8n8.x4.shared.b16 {%0,%1,%2,%3}, [%4];"
        : "=r"(r[0]), "=r"(r[1]), "=r"(r[2]), "=r"(r[3]) : "r"(addr));
}
__device__ __forceinline__ void ldsm_x4_t(uint32_t* r, uint32_t addr) {
    asm volatile("ldmatrix.sync.aligned.m8n8.x4.trans.shared.b16 {%0,%1,%2,%3}, [%4];"
        : "=r"(r[0]), "=r"(r[1]), "=r"(r[2]), "=r"(r[3]) : "r"(addr));
}
__device__ __forceinline__ void mma16816(float* c, const uint32_t* a, const uint32_t* b) {
    asm volatile(
        "mma.sync.aligned.m16n8k16.row.col.f32.f16.f16.f32 "
        "{%0,%1,%2,%3}, {%4,%5,%6,%7}, {%8,%9}, {%0,%1,%2,%3};"
        : "+f"(c[0]), "+f"(c[1]), "+f"(c[2]), "+f"(c[3])
        : "r"(a[0]), "r"(a[1]), "r"(a[2]), "r"(a[3]), "r"(b[0]), "r"(b[1]));
}

// ================= HGEMM: 128x128x32, 3-stage, 512 thr (32x32 warp)
// A [M,K] fp16 row-major, Bw [N,K] fp16 row-major
// EPI: 1 = +bias +res(fp16) -> TOUT, 2 = +bias +GELU -> fp16, 3 = plain -> fp16
template <int EPI, typename TOUT>
__global__ __launch_bounds__(512, 2) void hgemm(const __half* __restrict__ A,
                                                const __half* __restrict__ Bw,
                                                TOUT* __restrict__ C,
                                                int M, int N, int K,
                                                const float* __restrict__ bias,
                                                const __half* __restrict__ res)
{
    __shared__ __align__(16) char sm[3][16384];   // per stage: A 8KB, B 8KB
    const uint32_t smb = smem_u32(sm);

    const int tid = threadIdx.x;
    const int m0 = blockIdx.y * 128, n0 = blockIdx.x * 128;
    const int w = tid >> 5, lane = tid & 31;
    const int wm = w & 3, wn = w >> 2;            // 4x4 warps, warp tile 32x32

    // producer: 1 A chunk + 1 B chunk per thread per stage
    const int pr = tid >> 2, pch = tid & 3;       // row 0..127, chunk 0..3
    const __half* Apg = A  + (size_t)(m0 + pr) * K + pch * 8;
    const __half* Bpg = Bw + (size_t)(n0 + pr) * K + pch * 8;
    const uint32_t d0 = swz(pr, pch * 4);
    const int nstage = K >> 5;

    const int arow = wm * 32 + (lane & 15);       // + i*16
    const int achk = lane >> 4;
    const int brow = wn * 32 + (lane & 7) + ((lane >> 4) << 3);  // + jj*16
    const int bchk = (lane >> 3) & 1;

    float acc[2][4][4] = {};

#pragma unroll
    for (int s = 0; s < 2; s++) {
        uint32_t sb = smb + s * 16384;
        cpa16(sb + d0,        Apg + s * 32);
        cpa16(sb + 8192 + d0, Bpg + s * 32);
        CP_COMMIT();
    }

    for (int s = 0; s < nstage; s++) {
        if (s < nstage - 2) CP_WAIT1(); else CP_WAIT0();
        __syncthreads();

        if (s + 2 < nstage) {
            int st = s + 2;
            uint32_t sb = smb + (st % 3) * 16384;
            cpa16(sb + d0,        Apg + st * 32);
            cpa16(sb + 8192 + d0, Bpg + st * 32);
            CP_COMMIT();
        }

        const uint32_t aB = smb + (s % 3) * 16384;
        const uint32_t bB = aB + 8192;
#pragma unroll
        for (int kk = 0; kk < 2; kk++) {
            uint32_t afr[2][4], bfr[4][2];
#pragma unroll
            for (int i = 0; i < 2; i++)
                ldsm_x4(afr[i], aB + swz(arow + i * 16, (kk * 2 + achk) * 4));
#pragma unroll
            for (int jj = 0; jj < 2; jj++) {
                uint32_t r[4];
                ldsm_x4(r, bB + swz(brow + jj * 16, (kk * 2 + bchk) * 4));
                bfr[2 * jj][0] = r[0]; bfr[2 * jj][1] = r[1];
                bfr[2 * jj + 1][0] = r[2]; bfr[2 * jj + 1][1] = r[3];
            }
#pragma unroll
            for (int i = 0; i < 2; i++)
#pragma unroll
                for (int j = 0; j < 4; j++)
                    mma16816(acc[i][j], afr[i], bfr[j]);
        }
    }

    // ---- epilogue ----
    const int g = lane >> 2, tg = lane & 3;
#pragma unroll
    for (int i = 0; i < 2; i++) {
        const int r0 = m0 + wm * 32 + i * 16 + g;
#pragma unroll
        for (int j = 0; j < 4; j++) {
            const int c = n0 + wn * 32 + j * 8 + tg * 2;
            float v0 = acc[i][j][0], v1 = acc[i][j][1];
            float v2 = acc[i][j][2], v3 = acc[i][j][3];
            if (EPI == 1 || EPI == 2) {
                float bb0 = bias[c], bb1 = bias[c + 1];
                v0 += bb0; v1 += bb1; v2 += bb0; v3 += bb1;
            }
            if (EPI == 1) {
                __half2 r_a = *(const __half2*)(res + (size_t)r0 * N + c);
                __half2 r_b = *(const __half2*)(res + (size_t)(r0 + 8) * N + c);
                v0 += __low2float(r_a); v1 += __high2float(r_a);
                v2 += __low2float(r_b); v3 += __high2float(r_b);
                if (sizeof(TOUT) == 4) {
                    float* out = (float*)C;
                    *(float2*)(out + (size_t)r0 * N + c)       = make_float2(v0, v1);
                    *(float2*)(out + (size_t)(r0 + 8) * N + c) = make_float2(v2, v3);
                } else {
                    __half* out = (__half*)C;
                    *(__half2*)(out + (size_t)r0 * N + c)       = __floats2half2_rn(v0, v1);
                    *(__half2*)(out + (size_t)(r0 + 8) * N + c) = __floats2half2_rn(v2, v3);
                }
            } else if (EPI == 2) {
                v0 = 0.5f * v0 * (1.0f + erff(v0 * 0.70710678118654752f));
                v1 = 0.5f * v1 * (1.0f + erff(v1 * 0.70710678118654752f));
                v2 = 0.5f * v2 * (1.0f + erff(v2 * 0.70710678118654752f));
                v3 = 0.5f * v3 * (1.0f + erff(v3 * 0.70710678118654752f));
                __half* out = (__half*)C;
                *(__half2*)(out + (size_t)r0 * N + c)       = __floats2half2_rn(v0, v1);
                *(__half2*)(out + (size_t)(r0 + 8) * N + c) = __floats2half2_rn(v2, v3);
            } else {
                __half* out = (__half*)C;
                *(__half2*)(out + (size_t)r0 * N + c)       = __floats2half2_rn(v0, v1);
                *(__half2*)(out + (size_t)(r0 + 8) * N + c) = __floats2half2_rn(v2, v3);
            }
        }
    }
}

// -------- merged weight transpose+convert (all 4 matrices) ---------
__global__ __launch_bounds__(256) void wconv_all(const float* __restrict__ qkv_w,
                                                 const float* __restrict__ proj_w,
                                                 const float* __restrict__ fc1_w,
                                                 const float* __restrict__ fc2_w,
                                                 __half* __restrict__ hw)
{
    __shared__ float t[32][33];
    int bid = blockIdx.x;
    const float* in; __half* out; int K, N, tk, tn;
    if (bid < 768)       { in = qkv_w;  out = hw + OFF_QKV;  K = 512;  N = 1536; int r = bid;        tk = r & 15; tn = r >> 4; }
    else if (bid < 1024) { in = proj_w; out = hw + OFF_PROJ; K = 512;  N = 512;  int r = bid - 768;  tk = r & 15; tn = r >> 4; }
    else if (bid < 2048) { in = fc1_w;  out = hw + OFF_FC1;  K = 512;  N = 2048; int r = bid - 1024; tk = r & 15; tn = r >> 4; }
    else                 { in = fc2_w;  out = hw + OFF_FC2;  K = 2048; N = 512;  int r = bid - 2048; tk = r & 63; tn = r >> 6; }
    int k0 = tk * 32, n0 = tn * 32;
    int tx = threadIdx.x & 31, ty = threadIdx.x >> 5;
#pragma unroll
    for (int i = 0; i < 32; i += 8)
        t[ty + i][tx] = in[(size_t)(k0 + ty + i) * N + n0 + tx];
    __syncthreads();
#pragma unroll
    for (int i = 0; i < 32; i += 8)
        out[(size_t)(n0 + ty + i) * K + k0 + tx] = __float2half(t[tx][ty + i]);
}

// -------- pack conv weights (half2 pairs) + transpose cpe weights ---
__global__ void wpack(const float* __restrict__ w3, const float* __restrict__ w5,
                      const float* __restrict__ w7, const float* __restrict__ cw,
                      __half2* __restrict__ wp, float* __restrict__ cwT)
{
    int idx = blockIdx.x * blockDim.x + threadIdx.x;
    if (idx >= WPK_CPE) return;
    if (idx >= WPK_TOT) {
        int j = idx - WPK_TOT;          // 0..4607
        int t = j >> 9, c = j & 511;
        cwT[t * 512 + c] = cw[c * 9 + t];
        return;
    }
    const float* src; int p, t, KK;
    if (idx < WPK_W5)      { src = w3; int r = idx;           KK = 9;  p = r / 9;  t = r % 9;  }
    else if (idx < WPK_W7) { src = w5; int r = idx - WPK_W5;  KK = 25; p = r / 25; t = r % 25; }
    else                   { src = w7; int r = idx - WPK_W7;  KK = 49; p = r / 49; t = r % 49; }
    wp[idx] = __floats2half2_rn(src[(2 * p) * KK + t], src[(2 * p + 1) * KK + t]);
}

// ---------------- fused CPE (dw3x3 + residual) + LN1 ---------------
__global__ __launch_bounds__(128) void cpe_ln_k(const float* __restrict__ x,
                                                const float* __restrict__ cwT,
                                                const float* __restrict__ cb,
                                                const float* __restrict__ lw,
                                                const float* __restrict__ lb,
                                                __half* __restrict__ x0,
                                                __half* __restrict__ hA)
{
    int bn = blockIdx.x;
    int n = bn % NTOK;
    int bbase = bn - n;
    int yy = n / HH, xx = n - yy * HH;
    int tid = threadIdx.x;

    float s[4], outv[4];
#pragma unroll
    for (int u = 0; u < 4; u++) s[u] = cb[tid + u * 128];

#pragma unroll
    for (int ky = 0; ky < 3; ky++) {
        int iy = yy + ky - 1;
        if ((unsigned)iy >= (unsigned)HH) continue;
#pragma unroll
        for (int kx = 0; kx < 3; kx++) {
            int ix = xx + kx - 1;
            if ((unsigned)ix >= (unsigned)HH) continue;
            const float* xp = x + (size_t)(bbase + iy * HH + ix) * CDIM;
            const float* wt = cwT + (ky * 3 + kx) * 512;
#pragma unroll
            for (int u = 0; u < 4; u++) {
                int c = tid + u * 128;
                s[u] += __ldg(wt + c) * xp[c];
            }
        }
    }

    const float* xc = x + (size_t)bn * CDIM;
    float lsum = 0.0f;
#pragma unroll
    for (int u = 0; u < 4; u++) {
        int c = tid + u * 128;
        outv[u] = s[u] + xc[c];
        x0[(size_t)bn * CDIM + c] = __float2half(outv[u]);
        lsum += outv[u];
    }

    __shared__ float red[4];
    int lane = tid & 31, wid = tid >> 5;
#pragma unroll
    for (int o = 16; o > 0; o >>= 1) lsum += __shfl_xor_sync(0xffffffffu, lsum, o);
    if (lane == 0) red[wid] = lsum;
    __syncthreads();
    float mean = (red[0] + red[1] + red[2] + red[3]) * (1.0f / CDIM);
    __syncthreads();

    float q = 0.0f;
#pragma unroll
    for (int u = 0; u < 4; u++) { float d = outv[u] - mean; q += d * d; }
#pragma unroll
    for (int o = 16; o > 0; o >>= 1) q += __shfl_xor_sync(0xffffffffu, q, o);
    if (lane == 0) red[wid] = q;
    __syncthreads();
    float var = (red[0] + red[1] + red[2] + red[3]) * (1.0f / CDIM);
    float rstd = rsqrtf(var + 1e-6f);

#pragma unroll
    for (int u = 0; u < 4; u++) {
        int c = tid + u * 128;
        float v = (outv[u] - mean) * rstd * lw[c] + lb[c];
        hA[(size_t)bn * CDIM + c] = __float2half(v);
    }
}

// ---------------- LayerNorm over C=512 (fp16 in) -> fp16 out -------
__global__ __launch_bounds__(128) void ln_k(const __half* __restrict__ x,
                                            const float* __restrict__ w,
                                            const float* __restrict__ b,
                                            __half* __restrict__ y)
{
    int row = blockIdx.x;
    int tid = threadIdx.x;
    uint2 raw = *(const uint2*)(x + (size_t)row * CDIM + tid * 4);
    __half2 h0 = ((const __half2*)&raw)[0];
    __half2 h1 = ((const __half2*)&raw)[1];
    float4 v = make_float4(__low2float(h0), __high2float(h0),
                           __low2float(h1), __high2float(h1));
    __shared__ float red[4];
    int lane = tid & 31, wid = tid >> 5;

    float s = v.x + v.y + v.z + v.w;
#pragma unroll
    for (int o = 16; o > 0; o >>= 1) s += __shfl_xor_sync(0xffffffffu, s, o);
    if (lane == 0) red[wid] = s;
    __syncthreads();
    float mean = (red[0] + red[1] + red[2] + red[3]) * (1.0f / CDIM);
    __syncthreads();

    float4 d = make_float4(v.x - mean, v.y - mean, v.z - mean, v.w - mean);
    float q = d.x * d.x + d.y * d.y + d.z * d.z + d.w * d.w;
#pragma unroll
    for (int o = 16; o > 0; o >>= 1) q += __shfl_xor_sync(0xffffffffu, q, o);
    if (lane == 0) red[wid] = q;
    __syncthreads();
    float var = (red[0] + red[1] + red[2] + red[3]) * (1.0f / CDIM);
    float rstd = rsqrtf(var + 1e-6f);

    float4 wv = ((const float4*)w)[tid];
    float4 bv = ((const float4*)b)[tid];
    float ox = d.x * rstd * wv.x + bv.x;
    float oy = d.y * rstd * wv.y + bv.y;
    float oz = d.z * rstd * wv.z + bv.z;
    float ow = d.w * rstd * wv.w + bv.w;
    uint2 pack;
    ((__half2*)&pack)[0] = __floats2half2_rn(ox, oy);
    ((__half2*)&pack)[1] = __floats2half2_rn(oz, ow);
    *(uint2*)(y + (size_t)row * CDIM + tid * 4) = pack;
}

// ---------------- k-softmax statistics (32 chunks of 98 tokens) ----
__global__ __launch_bounds__(128) void kstats_part(const __half* __restrict__ qkv,
                                                   float* __restrict__ pmax,
                                                   float* __restrict__ psum, int B)
{
    int blk = blockIdx.x;
    int chunk = blk & 31;
    int hcg = (blk >> 5) & 3;
    int b = blk >> 7;
    int hc = hcg * 128 + threadIdx.x;
    const __half* kp = qkv + (size_t)b * NTOK * C3 + CDIM + hc;
    float m = -1e30f, s = 0.0f;
    int n0 = chunk * (NTOK / KSCH);
    for (int n = n0; n < n0 + NTOK / KSCH; n++) {
        float kx = __half2float(kp[(size_t)n * C3]);
        if (kx <= m) s += __expf(kx - m);
        else { s = s * __expf(m - kx) + 1.0f; m = kx; }
    }
    int BC = B * CDIM;
    pmax[chunk * BC + b * CDIM + hc] = m;
    psum[chunk * BC + b * CDIM + hc] = s;
}

__global__ void kstats_comb(const float* __restrict__ pmax, const float* __restrict__ psum,
                            float* __restrict__ kmax, float* __restrict__ kscale, int B)
{
    int idx = blockIdx.x * blockDim.x + threadIdx.x;
    int BC = B * CDIM;
    if (idx >= BC) return;
    float m = -1e30f, s = 0.0f;
#pragma unroll
    for (int c = 0; c < KSCH; c++) {
        float pm = pmax[c * BC + idx];
        float ps = psum[c * BC + idx];
        if (pm <= m) s += ps * __expf(pm - m);
        else { s = s * __expf(m - pm) + ps; m = pm; }
    }
    kmax[idx] = m;
    kscale[idx] = 1.0f / s;
}

// ---------------- kv partial via MMA: kvpart = E^T V ---------------
__global__ __launch_bounds__(128) void kvp_mma(const __half* __restrict__ qkv,
                                               const float* __restrict__ kmax,
                                               float* __restrict__ kvpart)
{
    __shared__ __align__(16) __half Es[64 * 64];
    __shared__ __align__(16) __half Vs[64 * 64];
    __shared__ float km[64];
    const uint32_t Eb = smem_u32(Es), Vb = smem_u32(Vs);

    int chunk = blockIdx.x % NCHUNK;
    int bh = blockIdx.x / NCHUNK;
    int b = bh >> 3, h = bh & 7;
    int tid = threadIdx.x, w = tid >> 5, lane = tid & 31;
    if (tid < 64) km[tid] = kmax[b * CDIM + h * CH + tid];
    __syncthreads();

    float acc[8][4] = {};
    const __half* base = qkv + (size_t)(b * NTOK + chunk * 448) * C3 + h * CH;

    const int pr = tid >> 1;
    const int pc0 = (tid & 1) * 4;

    for (int t0 = 0; t0 < 448; t0 += 64) {
        {
            const __half* vg = base + (size_t)(t0 + pr) * C3 + 2 * CDIM;
#pragma unroll
            for (int c = 0; c < 4; c++)
                cpa16(Vb + swz128(pr, pc0 + c), vg + (pc0 + c) * 8);
            CP_COMMIT();
        }
        {
            const __half* kg = base + (size_t)(t0 + pr) * C3 + CDIM;
#pragma unroll
            for (int c = 0; c < 4; c++) {
                uint4 raw = *(const uint4*)(kg + (pc0 + c) * 8);
                __half2* hp = (__half2*)&raw;
                uint4 outv;
                __half2* op = (__half2*)&outv;
#pragma unroll
                for (int t = 0; t < 4; t++) {
                    int cc = (pc0 + c) * 8 + t * 2;
                    float e0 = __expf(__low2float(hp[t])  - km[cc]);
                    float e1 = __expf(__high2float(hp[t]) - km[cc + 1]);
                    op[t] = __floats2half2_rn(e0, e1);
                }
                *(uint4*)((char*)Es + swz128(pr, pc0 + c)) = outv;
            }
        }
        CP_WAIT0();
        __syncthreads();

#pragma unroll
        for (int ts = 0; ts < 4; ts++) {
            int tb = ts * 16;
            uint32_t ar[4], afr[4];
            ldsm_x4_t(ar, Eb + swz128(tb + (lane & 15), 2 * w + (lane >> 4)));
            afr[0] = ar[0]; afr[1] = ar[2]; afr[2] = ar[1]; afr[3] = ar[3];

            uint32_t bfr[8][2];
#pragma unroll
            for (int p = 0; p < 4; p++) {
                uint32_t rr[4];
                ldsm_x4_t(rr, Vb + swz128(tb + (lane & 7) + (((lane >> 3) & 1) << 3),
                                          2 * p + (lane >> 4)));
                bfr[2 * p][0] = rr[0];     bfr[2 * p][1] = rr[1];
                bfr[2 * p + 1][0] = rr[2]; bfr[2 * p + 1][1] = rr[3];
            }
#pragma unroll
            for (int j = 0; j < 8; j++)
                mma16816(acc[j], afr, bfr[j]);
        }
        __syncthreads();
    }

    const int g = lane >> 2, tg = lane & 3;
    float* outp = kvpart + ((size_t)chunk * BMAX * NHEAD + bh) * 4096;
    const int r0 = 16 * w + g;
#pragma unroll
    for (int j = 0; j < 8; j++) {
        int c = j * 8 + tg * 2;
        *(float2*)(outp + r0 * 64 + c)       = make_float2(acc[j][0], acc[j][1]);
        *(float2*)(outp + (r0 + 8) * 64 + c) = make_float2(acc[j][2], acc[j][3]);
    }
}

// kv combine: apply 1/sum scale, emit fp16 kvT[v][k]
__global__ void kvcomb(const float* __restrict__ kvpart, const float* __restrict__ kscale,
                       __half* __restrict__ kvT, int B)
{
    int idx = blockIdx.x * blockDim.x + threadIdx.x;
    if (idx >= B * NHEAD * 4096) return;
    int bh = idx >> 12, e = idx & 4095;
    int k = e >> 6, v = e & 63;
    int b = bh >> 3, h = bh & 7;
    float s = 0.0f;
#pragma unroll
    for (int c = 0; c < NCHUNK; c++)
        s += kvpart[((size_t)c * BMAX * NHEAD + bh) * 4096 + e];
    s *= kscale[b * CDIM + h * CH + k];
    kvT[(size_t)bh * 4096 + v * 64 + k] = __float2half(s);
}

// ---------------- crpe conv on v: half2 taps (HFMA2) ---------------
__global__ void crpe_k(const __half* __restrict__ qkv,
                       const __half2* __restrict__ wpk,
                       const float* __restrict__ b3,
                       const float* __restrict__ b5,
                       const float* __restrict__ b7,
                       __half* __restrict__ attn, int total2)
{
    int idx = blockIdx.x * blockDim.x + threadIdx.x;
    if (idx >= total2) return;
    int pc = idx & 255;
    int hc = pc * 2;
    int bn = idx >> 8;
    int n = bn % NTOK;
    int bbase = bn - n;
    int yy = n / HH, xx = n - yy * HH;

    int K, P; const __half2* wp; float bb0, bb1;
    if (hc < 128)      { K = 3; P = 1; wp = wpk + pc * 9;                    bb0 = b3[hc];       bb1 = b3[hc + 1]; }
    else if (hc < 320) { K = 5; P = 2; wp = wpk + WPK_W5 + (pc - 64) * 25;   bb0 = b5[hc - 128]; bb1 = b5[hc - 127]; }
    else               { K = 7; P = 3; wp = wpk + WPK_W7 + (pc - 160) * 49;  bb0 = b7[hc - 320]; bb1 = b7[hc - 319]; }

    __half2 acc = __floats2half2_rn(bb0, bb1);
    const __half* vbase = qkv + 2 * CDIM + hc;
    for (int ky = 0; ky < K; ky++) {
        int iy = yy + ky - P;
        if ((unsigned)iy >= (unsigned)HH) continue;
        for (int kx = 0; kx < K; kx++) {
            int ix = xx + kx - P;
            if ((unsigned)ix >= (unsigned)HH) continue;
            __half2 v2 = *(const __half2*)(vbase + (size_t)(bbase + iy * HH + ix) * C3);
            acc = __hfma2(v2, __ldg(wp + ky * K + kx), acc);
        }
    }
    __half2 q2 = *(const __half2*)(qkv + (size_t)bn * C3 + hc);
    *(__half2*)(attn + (size_t)bn * CDIM + hc) = __hmul2(q2, acc);
}

// ---------------- factor att via MMA: hout = crpe + 0.125 q@kv -----
__global__ __launch_bounds__(128) void factor_mma(const __half* __restrict__ qkv,
                                                  const __half* __restrict__ kvT,
                                                  const __half* __restrict__ crpe,
                                                  __half* __restrict__ hout)
{
    __shared__ __align__(16) __half qs[64 * 64];
    __shared__ __align__(16) __half bs[64 * 64];
    const uint32_t qb = smem_u32(qs), bb = smem_u32(bs);

    int t = blockIdx.x;
    int tile = t % 49, bh = t / 49;
    int b = bh >> 3, h = bh & 7;
    int n0 = tile * 64;
    int tid = threadIdx.x, w = tid >> 5, lane = tid & 31;

    {
        int r = tid >> 1;
        int c0 = (tid & 1) * 4;
        const __half* qg = qkv + (size_t)(b * NTOK + n0 + r) * C3 + h * CH;
        const __half* kg = kvT + (size_t)bh * 4096 + r * 64;
#pragma unroll
        for (int c = 0; c < 4; c++) {
            cpa16(qb + swz128(r, c0 + c), qg + (c0 + c) * 8);
            cpa16(bb + swz128(r, c0 + c), kg + (c0 + c) * 8);
        }
        CP_COMMIT();
        CP_WAIT0();
    }
    __syncthreads();

    const int arow = w * 16 + (lane & 15);
    const int achk = lane >> 4;
    const int brow = (lane & 7) + ((lane >> 4) << 3);
    const int bchk = (lane >> 3) & 1;

    float acc[8][4] = {};
#pragma unroll
    for (int kk = 0; kk < 4; kk++) {
        uint32_t afr[4], bfr[8][2];
        ldsm_x4(afr, qb + swz128(arow, kk * 2 + achk));
#pragma unroll
        for (int jj = 0; jj < 4; jj++) {
            uint32_t rr[4];
            ldsm_x4(rr, bb + swz128(jj * 16 + brow, kk * 2 + bchk));
            bfr[2 * jj][0] = rr[0]; bfr[2 * jj][1] = rr[1];
            bfr[2 * jj + 1][0] = rr[2]; bfr[2 * jj + 1][1] = rr[3];
        }
#pragma unroll
        for (int j = 0; j < 8; j++)
            mma16816(acc[j], afr, bfr[j]);
    }

    const int g = lane >> 2, tg = lane & 3;
    const int row = n0 + w * 16 + g;
#pragma unroll
    for (int j = 0; j < 8; j++) {
        int c = j * 8 + tg * 2;
        size_t o0 = (size_t)(b * NTOK + row) * CDIM + h * CH + c;
        size_t o1 = o0 + (size_t)8 * CDIM;
        __half2 cr0 = *(const __half2*)(crpe + o0);
        __half2 cr1 = *(const __half2*)(crpe + o1);
        float v0 = __low2float(cr0)  + 0.125f * acc[j][0];
        float v1 = __high2float(cr0) + 0.125f * acc[j][1];
        float v2 = __low2float(cr1)  + 0.125f * acc[j][2];
        float v3 = __high2float(cr1) + 0.125f * acc[j][3];
        *(__half2*)(hout + o0) = __floats2half2_rn(v0, v1);
        *(__half2*)(hout + o1) = __floats2half2_rn(v2, v3);
    }
}

// ---------------- launch ------------------------------------------
extern "C" void kernel_launch(void* const* d_in, const int* in_sizes, int n_in,
                              void* d_out, int out_size)
{
    const float* x      = (const float*)d_in[0];
    const float* cpe_w  = (const float*)d_in[3];
    const float* cpe_b  = (const float*)d_in[4];
    const float* ln1_w  = (const float*)d_in[5];
    const float* ln1_b  = (const float*)d_in[6];
    const float* qkv_w  = (const float*)d_in[7];
    const float* proj_w = (const float*)d_in[8];
    const float* proj_b = (const float*)d_in[9];
    const float* w3     = (const float*)d_in[10];
    const float* b3     = (const float*)d_in[11];
    const float* w5     = (const float*)d_in[12];
    const float* b5     = (const float*)d_in[13];
    const float* w7     = (const float*)d_in[14];
    const float* b7     = (const float*)d_in[15];
    const float* ln2_w  = (const float*)d_in[16];
    const float* ln2_b  = (const float*)d_in[17];
    const float* fc1_w  = (const float*)d_in[18];
    const float* fc1_b  = (const float*)d_in[19];
    const float* fc2_w  = (const float*)d_in[20];
    const float* fc2_b  = (const float*)d_in[21];

    const int B = in_sizes[0] / (NTOK * CDIM);
    const int M = B * NTOK;

    float *kvpartp, *kmaxp, *kscalep, *pmaxp, *psump, *cwTp;
    __half *x0p, *x1p, *hAp, *hqkvp, *hHp, *hwp, *kvTp;
    __half2 *wpkp;
    cudaGetSymbolAddress((void**)&x0p, g_x0);
    cudaGetSymbolAddress((void**)&x1p, g_x1);
    cudaGetSymbolAddress((void**)&kvTp, g_kvT);
    cudaGetSymbolAddress((void**)&wpkp, g_wpk);
    cudaGetSymbolAddress((void**)&cwTp, g_cwT);
    cudaGetSymbolAddress((void**)&kvpartp, g_kvpart);
    cudaGetSymbolAddress((void**)&kmaxp, g_kmax);
    cudaGetSymbolAddress((void**)&kscalep, g_kscale);
    cudaGetSymbolAddress((void**)&pmaxp, g_pmax);
    cudaGetSymbolAddress((void**)&psump, g_psum);
    cudaGetSymbolAddress((void**)&hAp, g_hA);
    cudaGetSymbolAddress((void**)&hqkvp, g_hqkv);
    cudaGetSymbolAddress((void**)&hHp, g_hH);
    cudaGetSymbolAddress((void**)&hwp, g_hw);

    // second stream + events (host objects only; same graph every call)
    cudaStream_t s1;
    cudaStreamCreateWithFlags(&s1, cudaStreamNonBlocking);
    cudaEvent_t eFork0, eW, eQ, eK;
    cudaEventCreateWithFlags(&eFork0, cudaEventDisableTiming);
    cudaEventCreateWithFlags(&eW,     cudaEventDisableTiming);
    cudaEventCreateWithFlags(&eQ,     cudaEventDisableTiming);
    cudaEventCreateWithFlags(&eK,     cudaEventDisableTiming);

    // 0. weight packing on stream 0 (cpe_ln + crpe depend on it in-order)
    wpack<<<(WPK_CPE + 255) / 256, 256>>>(w3, w5, w7, cpe_w, wpkp, cwTp);

    // ---- fork: big weight transpose on s1 concurrent with CPE+LN1 ----
    cudaEventRecord(eFork0, 0);
    cudaStreamWaitEvent(s1, eFork0, 0);

    wconv_all<<<3072, 256, 0, s1>>>(qkv_w, proj_w, fc1_w, fc2_w, hwp);
    cpe_ln_k<<<M, 128>>>(x, cwTp, cpe_b, ln1_w, ln1_b, x0p, hAp);

    cudaEventRecord(eW, s1);
    cudaStreamWaitEvent(0, eW, 0);     // qkv GEMM needs weights

    // 2. qkv GEMM -> fp16 [M,1536]
    hgemm<3, __half><<<dim3(C3 / 128, M / 128), 512>>>(
        hAp, hwp + OFF_QKV, hqkvp, M, C3, CDIM, nullptr, nullptr);

    // ---- fork: kstats+kv chain on s1 concurrent with crpe on s0 ----
    cudaEventRecord(eQ, 0);
    cudaStreamWaitEvent(s1, eQ, 0);

    kstats_part<<<B * 128, 128, 0, s1>>>(hqkvp, pmaxp, psump, B);
    kstats_comb<<<(B * CDIM + 255) / 256, 256, 0, s1>>>(pmaxp, psump, kmaxp, kscalep, B);
    kvp_mma<<<B * NHEAD * NCHUNK, 128, 0, s1>>>(hqkvp, kmaxp, kvpartp);
    kvcomb<<<(B * NHEAD * 4096 + 255) / 256, 256, 0, s1>>>(kvpartp, kscalep, kvTp, B);

    crpe_k<<<(M * 256 + 255) / 256, 256>>>(hqkvp, wpkp, b3, b5, b7, hHp, M * 256);

    cudaEventRecord(eK, s1);
    cudaStreamWaitEvent(0, eK, 0);     // factor needs kvT

    // 6. factor attention via MMA -> fp16 attn (g_hA)
    factor_mma<<<B * NHEAD * 49, 128>>>(hqkvp, kvTp, hHp, hAp);
    // 7. proj GEMM + bias + residual(x0) -> x1 fp16
    hgemm<1, __half><<<dim3(CDIM / 128, M / 128), 512>>>(
        hAp, hwp + OFF_PROJ, x1p, M, CDIM, CDIM, proj_b, x0p);
    // 8. LN2 -> fp16
    ln_k<<<M, 128>>>(x1p, ln2_w, ln2_b, hAp);
    // 9. fc1 + bias + gelu -> fp16 hidden
    hgemm<2, __half><<<dim3(HID / 128, M / 128), 512>>>(
        hAp, hwp + OFF_FC1, hHp, M, HID, CDIM, fc1_b, nullptr);
    // 10. fc2 + bias + residual(x1) -> out fp32
    hgemm<1, float><<<dim3(CDIM / 128, M / 128), 512>>>(
        hHp, hwp + OFF_FC2, (float*)d_out, M, CDIM, HID, fc2_b, x1p);
}

// round 16
// speedup vs baseline: 1.0656x; 1.0656x over previous
#include <cuda_runtime.h>
#include <cuda_fp16.h>
#include <math.h>
#include <stdint.h>

// ---------------- problem constants (fixed shapes) ----------------
#define NTOK   3136       // 56*56
#define HH     56
#define CDIM   512
#define C3     1536
#define NHEAD  8
#define CH     64
#define HID    2048
#define BMAX   16
#define NCHUNK 7          // kv token chunks (7*448 = 3136)
#define KSCH   32         // kstats chunks (32*98 = 3136)

// packed conv weights: [0,576) w3 pairs, [576,2976) w5, [2976,7680) w7
#define WPK_W5 576
#define WPK_W7 2976
#define WPK_TOT 7680
#define WPK_CPE (WPK_TOT + 9 * 512)   // + cpe transpose

// ---------------- scratch (device globals; no allocations) --------
__device__ __half  g_x0  [(size_t)BMAX * NTOK * CDIM];
__device__ __half  g_x1  [(size_t)BMAX * NTOK * CDIM];
__device__ __half  g_hA  [(size_t)BMAX * NTOK * CDIM];
__device__ __half  g_hqkv[(size_t)BMAX * NTOK * C3];
__device__ __half  g_hH  [(size_t)BMAX * NTOK * HID];
__device__ __half  g_hw  [1536*512 + 512*512 + 2048*512 + 512*2048];
__device__ __half  g_kvT [BMAX * NHEAD * CH * CH];
__device__ __half2 g_wpk [WPK_TOT];
__device__ float   g_cwT [9 * 512];
__device__ float   g_kvpart[NCHUNK * BMAX * NHEAD * CH * CH];
__device__ float   g_kmax[BMAX * CDIM];
__device__ float   g_kscale[BMAX * CDIM];
__device__ float   g_pmax[KSCH * BMAX * CDIM];
__device__ float   g_psum[KSCH * BMAX * CDIM];

#define OFF_QKV  0
#define OFF_PROJ (1536*512)
#define OFF_FC1  (1536*512 + 512*512)
#define OFF_FC2  (1536*512 + 512*512 + 2048*512)

// ---------------- smem helpers -------------------------------------
__device__ __forceinline__ uint32_t smem_u32(const void* p) {
    uint32_t a;
    asm("{ .reg .u64 t; cvta.to.shared.u64 t, %1; cvt.u32.u64 %0, t; }" : "=r"(a) : "l"(p));
    return a;
}
__device__ __forceinline__ uint32_t swz(uint32_t r, uint32_t wp) {
    uint32_t off = r * 64 + wp * 4;
    return off ^ ((off >> 3) & 0x30);
}
__device__ __forceinline__ uint32_t swz128(uint32_t r, uint32_t ch) {
    return (r * 128 + ch * 16) ^ ((r & 7) << 4);
}
__device__ __forceinline__ void cpa16(uint32_t dst, const void* src) {
    asm volatile("cp.async.cg.shared.global [%0], [%1], 16;" :: "r"(dst), "l"(src));
}
#define CP_COMMIT() asm volatile("cp.async.commit_group;" ::: "memory")
#define CP_WAIT1()  asm volatile("cp.async.wait_group 1;" ::: "memory")
#define CP_WAIT0()  asm volatile("cp.async.wait_group 0;" ::: "memory")

__device__ __forceinline__ void ldsm_x4(uint32_t* r, uint32_t addr) {
    asm volatile("ldmatrix.sync.aligned.m8n8.x4.shared.b16 {%0,%1,%2,%3}, [%4];"
        : "=r"(r[0]), "=r"(r[1]), "=r"(r[2]), "=r"(r[3]) : "r"(addr));
}
__device__ __forceinline__ void ldsm_x4_t(uint32_t* r, uint32_t addr) {
    asm volatile("ldmatrix.sync.aligned.m8n8.x4.trans.shared.b16 {%0,%1,%2,%3}, [%4];"
        : "=r"(r[0]), "=r"(r[1]), "=r"(r[2]), "=r"(r[3]) : "r"(addr));
}
__device__ __forceinline__ void mma16816(float* c, const uint32_t* a, const uint32_t* b) {
    asm volatile(
        "mma.sync.aligned.m16n8k16.row.col.f32.f16.f16.f32 "
        "{%0,%1,%2,%3}, {%4,%5,%6,%7}, {%8,%9}, {%0,%1,%2,%3};"
        : "+f"(c[0]), "+f"(c[1]), "+f"(c[2]), "+f"(c[3])
        : "r"(a[0]), "r"(a[1]), "r"(a[2]), "r"(a[3]), "r"(b[0]), "r"(b[1]));
}

// ================= HGEMM: 128x128x32, 3-stage cp.async + ldmatrix ==
// (R14/R9 proven configuration — 256 thr, 64x32 warp tile)
template <int EPI, typename TOUT>
__global__ __launch_bounds__(256, 2) void hgemm(const __half* __restrict__ A,
                                                const __half* __restrict__ Bw,
                                                TOUT* __restrict__ C,
                                                int M, int N, int K,
                                                const float* __restrict__ bias,
                                                const __half* __restrict__ res)
{
    __shared__ __align__(16) char sm[3][16384];
    const uint32_t smb = smem_u32(sm);

    const int tid = threadIdx.x;
    const int m0 = blockIdx.y * 128, n0 = blockIdx.x * 128;
    const int w = tid >> 5, lane = tid & 31;
    const int wm = w & 1, wn = w >> 1;

    const int pr = tid >> 2, pch = tid & 3;
    const __half* Apg = A  + (size_t)(m0 + pr) * K + pch * 8;
    const __half* Bpg = Bw + (size_t)(n0 + pr) * K + pch * 8;
    const uint32_t d0 = swz(pr, pch * 4);
    const uint32_t d1 = swz(pr + 64, pch * 4);
    const int nstage = K >> 5;

    const int arow = wm * 64 + (lane & 15);
    const int achk = lane >> 4;
    const int brow = wn * 32 + (lane & 7) + ((lane >> 4) << 3);
    const int bchk = (lane >> 3) & 1;

    float acc[4][4][4] = {};

#pragma unroll
    for (int s = 0; s < 2; s++) {
        uint32_t sb = smb + s * 16384;
        cpa16(sb + d0,        Apg + s * 32);
        cpa16(sb + d1,        Apg + (size_t)64 * K + s * 32);
        cpa16(sb + 8192 + d0, Bpg + s * 32);
        cpa16(sb + 8192 + d1, Bpg + (size_t)64 * K + s * 32);
        CP_COMMIT();
    }

    for (int s = 0; s < nstage; s++) {
        if (s < nstage - 2) CP_WAIT1(); else CP_WAIT0();
        __syncthreads();

        if (s + 2 < nstage) {
            int st = s + 2;
            uint32_t sb = smb + (st % 3) * 16384;
            cpa16(sb + d0,        Apg + st * 32);
            cpa16(sb + d1,        Apg + (size_t)64 * K + st * 32);
            cpa16(sb + 8192 + d0, Bpg + st * 32);
            cpa16(sb + 8192 + d1, Bpg + (size_t)64 * K + st * 32);
            CP_COMMIT();
        }

        const uint32_t aB = smb + (s % 3) * 16384;
        const uint32_t bB = aB + 8192;
#pragma unroll
        for (int kk = 0; kk < 2; kk++) {
            uint32_t afr[4][4], bfr[4][2];
#pragma unroll
            for (int i = 0; i < 4; i++)
                ldsm_x4(afr[i], aB + swz(arow + i * 16, (kk * 2 + achk) * 4));
#pragma unroll
            for (int jj = 0; jj < 2; jj++) {
                uint32_t r[4];
                ldsm_x4(r, bB + swz(brow + jj * 16, (kk * 2 + bchk) * 4));
                bfr[2 * jj][0] = r[0]; bfr[2 * jj][1] = r[1];
                bfr[2 * jj + 1][0] = r[2]; bfr[2 * jj + 1][1] = r[3];
            }
#pragma unroll
            for (int i = 0; i < 4; i++)
#pragma unroll
                for (int j = 0; j < 4; j++)
                    mma16816(acc[i][j], afr[i], bfr[j]);
        }
    }

    // ---- epilogue ----
    const int g = lane >> 2, tg = lane & 3;
#pragma unroll
    for (int i = 0; i < 4; i++) {
        const int r0 = m0 + wm * 64 + i * 16 + g;
#pragma unroll
        for (int j = 0; j < 4; j++) {
            const int c = n0 + wn * 32 + j * 8 + tg * 2;
            float v0 = acc[i][j][0], v1 = acc[i][j][1];
            float v2 = acc[i][j][2], v3 = acc[i][j][3];
            if (EPI == 1 || EPI == 2) {
                float bb0 = bias[c], bb1 = bias[c + 1];
                v0 += bb0; v1 += bb1; v2 += bb0; v3 += bb1;
            }
            if (EPI == 1) {
                __half2 r_a = *(const __half2*)(res + (size_t)r0 * N + c);
                __half2 r_b = *(const __half2*)(res + (size_t)(r0 + 8) * N + c);
                v0 += __low2float(r_a); v1 += __high2float(r_a);
                v2 += __low2float(r_b); v3 += __high2float(r_b);
                if (sizeof(TOUT) == 4) {
                    float* out = (float*)C;
                    *(float2*)(out + (size_t)r0 * N + c)       = make_float2(v0, v1);
                    *(float2*)(out + (size_t)(r0 + 8) * N + c) = make_float2(v2, v3);
                } else {
                    __half* out = (__half*)C;
                    *(__half2*)(out + (size_t)r0 * N + c)       = __floats2half2_rn(v0, v1);
                    *(__half2*)(out + (size_t)(r0 + 8) * N + c) = __floats2half2_rn(v2, v3);
                }
            } else if (EPI == 2) {
                v0 = 0.5f * v0 * (1.0f + erff(v0 * 0.70710678118654752f));
                v1 = 0.5f * v1 * (1.0f + erff(v1 * 0.70710678118654752f));
                v2 = 0.5f * v2 * (1.0f + erff(v2 * 0.70710678118654752f));
                v3 = 0.5f * v3 * (1.0f + erff(v3 * 0.70710678118654752f));
                __half* out = (__half*)C;
                *(__half2*)(out + (size_t)r0 * N + c)       = __floats2half2_rn(v0, v1);
                *(__half2*)(out + (size_t)(r0 + 8) * N + c) = __floats2half2_rn(v2, v3);
            } else {
                __half* out = (__half*)C;
                *(__half2*)(out + (size_t)r0 * N + c)       = __floats2half2_rn(v0, v1);
                *(__half2*)(out + (size_t)(r0 + 8) * N + c) = __floats2half2_rn(v2, v3);
            }
        }
    }
}

// -------- merged weight transpose+convert (all 4 matrices) ---------
__global__ __launch_bounds__(256) void wconv_all(const float* __restrict__ qkv_w,
                                                 const float* __restrict__ proj_w,
                                                 const float* __restrict__ fc1_w,
                                                 const float* __restrict__ fc2_w,
                                                 __half* __restrict__ hw)
{
    __shared__ float t[32][33];
    int bid = blockIdx.x;
    const float* in; __half* out; int K, N, tk, tn;
    if (bid < 768)       { in = qkv_w;  out = hw + OFF_QKV;  K = 512;  N = 1536; int r = bid;        tk = r & 15; tn = r >> 4; }
    else if (bid < 1024) { in = proj_w; out = hw + OFF_PROJ; K = 512;  N = 512;  int r = bid - 768;  tk = r & 15; tn = r >> 4; }
    else if (bid < 2048) { in = fc1_w;  out = hw + OFF_FC1;  K = 512;  N = 2048; int r = bid - 1024; tk = r & 15; tn = r >> 4; }
    else                 { in = fc2_w;  out = hw + OFF_FC2;  K = 2048; N = 512;  int r = bid - 2048; tk = r & 63; tn = r >> 6; }
    int k0 = tk * 32, n0 = tn * 32;
    int tx = threadIdx.x & 31, ty = threadIdx.x >> 5;
#pragma unroll
    for (int i = 0; i < 32; i += 8)
        t[ty + i][tx] = in[(size_t)(k0 + ty + i) * N + n0 + tx];
    __syncthreads();
#pragma unroll
    for (int i = 0; i < 32; i += 8)
        out[(size_t)(n0 + ty + i) * K + k0 + tx] = __float2half(t[tx][ty + i]);
}

// -------- pack conv weights (half2 pairs) + transpose cpe weights ---
__global__ void wpack(const float* __restrict__ w3, const float* __restrict__ w5,
                      const float* __restrict__ w7, const float* __restrict__ cw,
                      __half2* __restrict__ wp, float* __restrict__ cwT)
{
    int idx = blockIdx.x * blockDim.x + threadIdx.x;
    if (idx >= WPK_CPE) return;
    if (idx >= WPK_TOT) {
        int j = idx - WPK_TOT;          // 0..4607
        int t = j >> 9, c = j & 511;
        cwT[t * 512 + c] = cw[c * 9 + t];
        return;
    }
    const float* src; int p, t, KK;
    if (idx < WPK_W5)      { src = w3; int r = idx;           KK = 9;  p = r / 9;  t = r % 9;  }
    else if (idx < WPK_W7) { src = w5; int r = idx - WPK_W5;  KK = 25; p = r / 25; t = r % 25; }
    else                   { src = w7; int r = idx - WPK_W7;  KK = 49; p = r / 49; t = r % 49; }
    wp[idx] = __floats2half2_rn(src[(2 * p) * KK + t], src[(2 * p + 1) * KK + t]);
}

// ---------------- fused CPE (dw3x3 + residual) + LN1 ---------------
__global__ __launch_bounds__(128) void cpe_ln_k(const float* __restrict__ x,
                                                const float* __restrict__ cwT,
                                                const float* __restrict__ cb,
                                                const float* __restrict__ lw,
                                                const float* __restrict__ lb,
                                                __half* __restrict__ x0,
                                                __half* __restrict__ hA)
{
    int bn = blockIdx.x;
    int n = bn % NTOK;
    int bbase = bn - n;
    int yy = n / HH, xx = n - yy * HH;
    int tid = threadIdx.x;

    float s[4], outv[4];
#pragma unroll
    for (int u = 0; u < 4; u++) s[u] = cb[tid + u * 128];

#pragma unroll
    for (int ky = 0; ky < 3; ky++) {
        int iy = yy + ky - 1;
        if ((unsigned)iy >= (unsigned)HH) continue;
#pragma unroll
        for (int kx = 0; kx < 3; kx++) {
            int ix = xx + kx - 1;
            if ((unsigned)ix >= (unsigned)HH) continue;
            const float* xp = x + (size_t)(bbase + iy * HH + ix) * CDIM;
            const float* wt = cwT + (ky * 3 + kx) * 512;
#pragma unroll
            for (int u = 0; u < 4; u++) {
                int c = tid + u * 128;
                s[u] += __ldg(wt + c) * xp[c];
            }
        }
    }

    const float* xc = x + (size_t)bn * CDIM;
    float lsum = 0.0f;
#pragma unroll
    for (int u = 0; u < 4; u++) {
        int c = tid + u * 128;
        outv[u] = s[u] + xc[c];
        x0[(size_t)bn * CDIM + c] = __float2half(outv[u]);
        lsum += outv[u];
    }

    __shared__ float red[4];
    int lane = tid & 31, wid = tid >> 5;
#pragma unroll
    for (int o = 16; o > 0; o >>= 1) lsum += __shfl_xor_sync(0xffffffffu, lsum, o);
    if (lane == 0) red[wid] = lsum;
    __syncthreads();
    float mean = (red[0] + red[1] + red[2] + red[3]) * (1.0f / CDIM);
    __syncthreads();

    float q = 0.0f;
#pragma unroll
    for (int u = 0; u < 4; u++) { float d = outv[u] - mean; q += d * d; }
#pragma unroll
    for (int o = 16; o > 0; o >>= 1) q += __shfl_xor_sync(0xffffffffu, q, o);
    if (lane == 0) red[wid] = q;
    __syncthreads();
    float var = (red[0] + red[1] + red[2] + red[3]) * (1.0f / CDIM);
    float rstd = rsqrtf(var + 1e-6f);

#pragma unroll
    for (int u = 0; u < 4; u++) {
        int c = tid + u * 128;
        float v = (outv[u] - mean) * rstd * lw[c] + lb[c];
        hA[(size_t)bn * CDIM + c] = __float2half(v);
    }
}

// ---------------- LayerNorm over C=512 (fp16 in) -> fp16 out -------
__global__ __launch_bounds__(128) void ln_k(const __half* __restrict__ x,
                                            const float* __restrict__ w,
                                            const float* __restrict__ b,
                                            __half* __restrict__ y)
{
    int row = blockIdx.x;
    int tid = threadIdx.x;
    uint2 raw = *(const uint2*)(x + (size_t)row * CDIM + tid * 4);
    __half2 h0 = ((const __half2*)&raw)[0];
    __half2 h1 = ((const __half2*)&raw)[1];
    float4 v = make_float4(__low2float(h0), __high2float(h0),
                           __low2float(h1), __high2float(h1));
    __shared__ float red[4];
    int lane = tid & 31, wid = tid >> 5;

    float s = v.x + v.y + v.z + v.w;
#pragma unroll
    for (int o = 16; o > 0; o >>= 1) s += __shfl_xor_sync(0xffffffffu, s, o);
    if (lane == 0) red[wid] = s;
    __syncthreads();
    float mean = (red[0] + red[1] + red[2] + red[3]) * (1.0f / CDIM);
    __syncthreads();

    float4 d = make_float4(v.x - mean, v.y - mean, v.z - mean, v.w - mean);
    float q = d.x * d.x + d.y * d.y + d.z * d.z + d.w * d.w;
#pragma unroll
    for (int o = 16; o > 0; o >>= 1) q += __shfl_xor_sync(0xffffffffu, q, o);
    if (lane == 0) red[wid] = q;
    __syncthreads();
    float var = (red[0] + red[1] + red[2] + red[3]) * (1.0f / CDIM);
    float rstd = rsqrtf(var + 1e-6f);

    float4 wv = ((const float4*)w)[tid];
    float4 bv = ((const float4*)b)[tid];
    float ox = d.x * rstd * wv.x + bv.x;
    float oy = d.y * rstd * wv.y + bv.y;
    float oz = d.z * rstd * wv.z + bv.z;
    float ow = d.w * rstd * wv.w + bv.w;
    uint2 pack;
    ((__half2*)&pack)[0] = __floats2half2_rn(ox, oy);
    ((__half2*)&pack)[1] = __floats2half2_rn(oz, ow);
    *(uint2*)(y + (size_t)row * CDIM + tid * 4) = pack;
}

// ---------------- k-softmax statistics (32 chunks of 98 tokens) ----
__global__ __launch_bounds__(128) void kstats_part(const __half* __restrict__ qkv,
                                                   float* __restrict__ pmax,
                                                   float* __restrict__ psum, int B)
{
    int blk = blockIdx.x;
    int chunk = blk & 31;
    int hcg = (blk >> 5) & 3;
    int b = blk >> 7;
    int hc = hcg * 128 + threadIdx.x;
    const __half* kp = qkv + (size_t)b * NTOK * C3 + CDIM + hc;
    float m = -1e30f, s = 0.0f;
    int n0 = chunk * (NTOK / KSCH);
    for (int n = n0; n < n0 + NTOK / KSCH; n++) {
        float kx = __half2float(kp[(size_t)n * C3]);
        if (kx <= m) s += __expf(kx - m);
        else { s = s * __expf(m - kx) + 1.0f; m = kx; }
    }
    int BC = B * CDIM;
    pmax[chunk * BC + b * CDIM + hc] = m;
    psum[chunk * BC + b * CDIM + hc] = s;
}

__global__ void kstats_comb(const float* __restrict__ pmax, const float* __restrict__ psum,
                            float* __restrict__ kmax, float* __restrict__ kscale, int B)
{
    int idx = blockIdx.x * blockDim.x + threadIdx.x;
    int BC = B * CDIM;
    if (idx >= BC) return;
    float m = -1e30f, s = 0.0f;
#pragma unroll
    for (int c = 0; c < KSCH; c++) {
        float pm = pmax[c * BC + idx];
        float ps = psum[c * BC + idx];
        if (pm <= m) s += ps * __expf(pm - m);
        else { s = s * __expf(m - pm) + ps; m = pm; }
    }
    kmax[idx] = m;
    kscale[idx] = 1.0f / s;
}

// ---------------- kv partial via MMA: kvpart = E^T V ---------------
__global__ __launch_bounds__(128) void kvp_mma(const __half* __restrict__ qkv,
                                               const float* __restrict__ kmax,
                                               float* __restrict__ kvpart)
{
    __shared__ __align__(16) __half Es[64 * 64];
    __shared__ __align__(16) __half Vs[64 * 64];
    __shared__ float km[64];
    const uint32_t Eb = smem_u32(Es), Vb = smem_u32(Vs);

    int chunk = blockIdx.x % NCHUNK;
    int bh = blockIdx.x / NCHUNK;
    int b = bh >> 3, h = bh & 7;
    int tid = threadIdx.x, w = tid >> 5, lane = tid & 31;
    if (tid < 64) km[tid] = kmax[b * CDIM + h * CH + tid];
    __syncthreads();

    float acc[8][4] = {};
    const __half* base = qkv + (size_t)(b * NTOK + chunk * 448) * C3 + h * CH;

    const int pr = tid >> 1;
    const int pc0 = (tid & 1) * 4;

    for (int t0 = 0; t0 < 448; t0 += 64) {
        {
            const __half* vg = base + (size_t)(t0 + pr) * C3 + 2 * CDIM;
#pragma unroll
            for (int c = 0; c < 4; c++)
                cpa16(Vb + swz128(pr, pc0 + c), vg + (pc0 + c) * 8);
            CP_COMMIT();
        }
        {
            const __half* kg = base + (size_t)(t0 + pr) * C3 + CDIM;
#pragma unroll
            for (int c = 0; c < 4; c++) {
                uint4 raw = *(const uint4*)(kg + (pc0 + c) * 8);
                __half2* hp = (__half2*)&raw;
                uint4 outv;
                __half2* op = (__half2*)&outv;
#pragma unroll
                for (int t = 0; t < 4; t++) {
                    int cc = (pc0 + c) * 8 + t * 2;
                    float e0 = __expf(__low2float(hp[t])  - km[cc]);
                    float e1 = __expf(__high2float(hp[t]) - km[cc + 1]);
                    op[t] = __floats2half2_rn(e0, e1);
                }
                *(uint4*)((char*)Es + swz128(pr, pc0 + c)) = outv;
            }
        }
        CP_WAIT0();
        __syncthreads();

#pragma unroll
        for (int ts = 0; ts < 4; ts++) {
            int tb = ts * 16;
            uint32_t ar[4], afr[4];
            ldsm_x4_t(ar, Eb + swz128(tb + (lane & 15), 2 * w + (lane >> 4)));
            afr[0] = ar[0]; afr[1] = ar[2]; afr[2] = ar[1]; afr[3] = ar[3];

            uint32_t bfr[8][2];
#pragma unroll
            for (int p = 0; p < 4; p++) {
                uint32_t rr[4];
                ldsm_x4_t(rr, Vb + swz128(tb + (lane & 7) + (((lane >> 3) & 1) << 3),
                                          2 * p + (lane >> 4)));
                bfr[2 * p][0] = rr[0];     bfr[2 * p][1] = rr[1];
                bfr[2 * p + 1][0] = rr[2]; bfr[2 * p + 1][1] = rr[3];
            }
#pragma unroll
            for (int j = 0; j < 8; j++)
                mma16816(acc[j], afr, bfr[j]);
        }
        __syncthreads();
    }

    const int g = lane >> 2, tg = lane & 3;
    float* outp = kvpart + ((size_t)chunk * BMAX * NHEAD + bh) * 4096;
    const int r0 = 16 * w + g;
#pragma unroll
    for (int j = 0; j < 8; j++) {
        int c = j * 8 + tg * 2;
        *(float2*)(outp + r0 * 64 + c)       = make_float2(acc[j][0], acc[j][1]);
        *(float2*)(outp + (r0 + 8) * 64 + c) = make_float2(acc[j][2], acc[j][3]);
    }
}

// kv combine: apply 1/sum scale, emit fp16 kvT[v][k]
__global__ void kvcomb(const float* __restrict__ kvpart, const float* __restrict__ kscale,
                       __half* __restrict__ kvT, int B)
{
    int idx = blockIdx.x * blockDim.x + threadIdx.x;
    if (idx >= B * NHEAD * 4096) return;
    int bh = idx >> 12, e = idx & 4095;
    int k = e >> 6, v = e & 63;
    int b = bh >> 3, h = bh & 7;
    float s = 0.0f;
#pragma unroll
    for (int c = 0; c < NCHUNK; c++)
        s += kvpart[((size_t)c * BMAX * NHEAD + bh) * 4096 + e];
    s *= kscale[b * CDIM + h * CH + k];
    kvT[(size_t)bh * 4096 + v * 64 + k] = __float2half(s);
}

// ---------------- crpe conv on v: half2 taps (HFMA2) ---------------
__global__ void crpe_k(const __half* __restrict__ qkv,
                       const __half2* __restrict__ wpk,
                       const float* __restrict__ b3,
                       const float* __restrict__ b5,
                       const float* __restrict__ b7,
                       __half* __restrict__ attn, int total2)
{
    int idx = blockIdx.x * blockDim.x + threadIdx.x;
    if (idx >= total2) return;
    int pc = idx & 255;
    int hc = pc * 2;
    int bn = idx >> 8;
    int n = bn % NTOK;
    int bbase = bn - n;
    int yy = n / HH, xx = n - yy * HH;

    int K, P; const __half2* wp; float bb0, bb1;
    if (hc < 128)      { K = 3; P = 1; wp = wpk + pc * 9;                    bb0 = b3[hc];       bb1 = b3[hc + 1]; }
    else if (hc < 320) { K = 5; P = 2; wp = wpk + WPK_W5 + (pc - 64) * 25;   bb0 = b5[hc - 128]; bb1 = b5[hc - 127]; }
    else               { K = 7; P = 3; wp = wpk + WPK_W7 + (pc - 160) * 49;  bb0 = b7[hc - 320]; bb1 = b7[hc - 319]; }

    __half2 acc = __floats2half2_rn(bb0, bb1);
    const __half* vbase = qkv + 2 * CDIM + hc;
    for (int ky = 0; ky < K; ky++) {
        int iy = yy + ky - P;
        if ((unsigned)iy >= (unsigned)HH) continue;
        for (int kx = 0; kx < K; kx++) {
            int ix = xx + kx - P;
            if ((unsigned)ix >= (unsigned)HH) continue;
            __half2 v2 = *(const __half2*)(vbase + (size_t)(bbase + iy * HH + ix) * C3);
            acc = __hfma2(v2, __ldg(wp + ky * K + kx), acc);
        }
    }
    __half2 q2 = *(const __half2*)(qkv + (size_t)bn * C3 + hc);
    *(__half2*)(attn + (size_t)bn * CDIM + hc) = __hmul2(q2, acc);
}

// ---------------- factor att via MMA: hout = crpe + 0.125 q@kv -----
__global__ __launch_bounds__(128) void factor_mma(const __half* __restrict__ qkv,
                                                  const __half* __restrict__ kvT,
                                                  const __half* __restrict__ crpe,
                                                  __half* __restrict__ hout)
{
    __shared__ __align__(16) __half qs[64 * 64];
    __shared__ __align__(16) __half bs[64 * 64];
    const uint32_t qb = smem_u32(qs), bb = smem_u32(bs);

    int t = blockIdx.x;
    int tile = t % 49, bh = t / 49;
    int b = bh >> 3, h = bh & 7;
    int n0 = tile * 64;
    int tid = threadIdx.x, w = tid >> 5, lane = tid & 31;

    {
        int r = tid >> 1;
        int c0 = (tid & 1) * 4;
        const __half* qg = qkv + (size_t)(b * NTOK + n0 + r) * C3 + h * CH;
        const __half* kg = kvT + (size_t)bh * 4096 + r * 64;
#pragma unroll
        for (int c = 0; c < 4; c++) {
            cpa16(qb + swz128(r, c0 + c), qg + (c0 + c) * 8);
            cpa16(bb + swz128(r, c0 + c), kg + (c0 + c) * 8);
        }
        CP_COMMIT();
        CP_WAIT0();
    }
    __syncthreads();

    const int arow = w * 16 + (lane & 15);
    const int achk = lane >> 4;
    const int brow = (lane & 7) + ((lane >> 4) << 3);
    const int bchk = (lane >> 3) & 1;

    float acc[8][4] = {};
#pragma unroll
    for (int kk = 0; kk < 4; kk++) {
        uint32_t afr[4], bfr[8][2];
        ldsm_x4(afr, qb + swz128(arow, kk * 2 + achk));
#pragma unroll
        for (int jj = 0; jj < 4; jj++) {
            uint32_t rr[4];
            ldsm_x4(rr, bb + swz128(jj * 16 + brow, kk * 2 + bchk));
            bfr[2 * jj][0] = rr[0]; bfr[2 * jj][1] = rr[1];
            bfr[2 * jj + 1][0] = rr[2]; bfr[2 * jj + 1][1] = rr[3];
        }
#pragma unroll
        for (int j = 0; j < 8; j++)
            mma16816(acc[j], afr, bfr[j]);
    }

    const int g = lane >> 2, tg = lane & 3;
    const int row = n0 + w * 16 + g;
#pragma unroll
    for (int j = 0; j < 8; j++) {
        int c = j * 8 + tg * 2;
        size_t o0 = (size_t)(b * NTOK + row) * CDIM + h * CH + c;
        size_t o1 = o0 + (size_t)8 * CDIM;
        __half2 cr0 = *(const __half2*)(crpe + o0);
        __half2 cr1 = *(const __half2*)(crpe + o1);
        float v0 = __low2float(cr0)  + 0.125f * acc[j][0];
        float v1 = __high2float(cr0) + 0.125f * acc[j][1];
        float v2 = __low2float(cr1)  + 0.125f * acc[j][2];
        float v3 = __high2float(cr1) + 0.125f * acc[j][3];
        *(__half2*)(hout + o0) = __floats2half2_rn(v0, v1);
        *(__half2*)(hout + o1) = __floats2half2_rn(v2, v3);
    }
}

// ---------------- launch ------------------------------------------
extern "C" void kernel_launch(void* const* d_in, const int* in_sizes, int n_in,
                              void* d_out, int out_size)
{
    const float* x      = (const float*)d_in[0];
    const float* cpe_w  = (const float*)d_in[3];
    const float* cpe_b  = (const float*)d_in[4];
    const float* ln1_w  = (const float*)d_in[5];
    const float* ln1_b  = (const float*)d_in[6];
    const float* qkv_w  = (const float*)d_in[7];
    const float* proj_w = (const float*)d_in[8];
    const float* proj_b = (const float*)d_in[9];
    const float* w3     = (const float*)d_in[10];
    const float* b3     = (const float*)d_in[11];
    const float* w5     = (const float*)d_in[12];
    const float* b5     = (const float*)d_in[13];
    const float* w7     = (const float*)d_in[14];
    const float* b7     = (const float*)d_in[15];
    const float* ln2_w  = (const float*)d_in[16];
    const float* ln2_b  = (const float*)d_in[17];
    const float* fc1_w  = (const float*)d_in[18];
    const float* fc1_b  = (const float*)d_in[19];
    const float* fc2_w  = (const float*)d_in[20];
    const float* fc2_b  = (const float*)d_in[21];

    const int B = in_sizes[0] / (NTOK * CDIM);
    const int M = B * NTOK;

    float *kvpartp, *kmaxp, *kscalep, *pmaxp, *psump, *cwTp;
    __half *x0p, *x1p, *hAp, *hqkvp, *hHp, *hwp, *kvTp;
    __half2 *wpkp;
    cudaGetSymbolAddress((void**)&x0p, g_x0);
    cudaGetSymbolAddress((void**)&x1p, g_x1);
    cudaGetSymbolAddress((void**)&kvTp, g_kvT);
    cudaGetSymbolAddress((void**)&wpkp, g_wpk);
    cudaGetSymbolAddress((void**)&cwTp, g_cwT);
    cudaGetSymbolAddress((void**)&kvpartp, g_kvpart);
    cudaGetSymbolAddress((void**)&kmaxp, g_kmax);
    cudaGetSymbolAddress((void**)&kscalep, g_kscale);
    cudaGetSymbolAddress((void**)&pmaxp, g_pmax);
    cudaGetSymbolAddress((void**)&psump, g_psum);
    cudaGetSymbolAddress((void**)&hAp, g_hA);
    cudaGetSymbolAddress((void**)&hqkvp, g_hqkv);
    cudaGetSymbolAddress((void**)&hHp, g_hH);
    cudaGetSymbolAddress((void**)&hwp, g_hw);

    // second stream + events (host objects only; same graph every call)
    cudaStream_t s1;
    cudaStreamCreateWithFlags(&s1, cudaStreamNonBlocking);
    cudaEvent_t eFork0, eW, eQ, eK;
    cudaEventCreateWithFlags(&eFork0, cudaEventDisableTiming);
    cudaEventCreateWithFlags(&eW,     cudaEventDisableTiming);
    cudaEventCreateWithFlags(&eQ,     cudaEventDisableTiming);
    cudaEventCreateWithFlags(&eK,     cudaEventDisableTiming);

    // 0. weight packing on stream 0 (cpe_ln + crpe depend on it in-order)
    wpack<<<(WPK_CPE + 255) / 256, 256>>>(w3, w5, w7, cpe_w, wpkp, cwTp);

    // ---- fork: big weight transpose on s1 concurrent with CPE+LN1 ----
    cudaEventRecord(eFork0, 0);
    cudaStreamWaitEvent(s1, eFork0, 0);

    wconv_all<<<3072, 256, 0, s1>>>(qkv_w, proj_w, fc1_w, fc2_w, hwp);
    cpe_ln_k<<<M, 128>>>(x, cwTp, cpe_b, ln1_w, ln1_b, x0p, hAp);

    cudaEventRecord(eW, s1);
    cudaStreamWaitEvent(0, eW, 0);     // qkv GEMM needs weights

    // 2. qkv GEMM -> fp16 [M,1536]
    hgemm<3, __half><<<dim3(C3 / 128, M / 128), 256>>>(
        hAp, hwp + OFF_QKV, hqkvp, M, C3, CDIM, nullptr, nullptr);

    // ---- fork: kstats+kv chain on s1 concurrent with crpe on s0 ----
    cudaEventRecord(eQ, 0);
    cudaStreamWaitEvent(s1, eQ, 0);

    kstats_part<<<B * 128, 128, 0, s1>>>(hqkvp, pmaxp, psump, B);
    kstats_comb<<<(B * CDIM + 255) / 256, 256, 0, s1>>>(pmaxp, psump, kmaxp, kscalep, B);
    kvp_mma<<<B * NHEAD * NCHUNK, 128, 0, s1>>>(hqkvp, kmaxp, kvpartp);
    kvcomb<<<(B * NHEAD * 4096 + 255) / 256, 256, 0, s1>>>(kvpartp, kscalep, kvTp, B);

    crpe_k<<<(M * 256 + 255) / 256, 256>>>(hqkvp, wpkp, b3, b5, b7, hHp, M * 256);

    cudaEventRecord(eK, s1);
    cudaStreamWaitEvent(0, eK, 0);     // factor needs kvT

    // 6. factor attention via MMA -> fp16 attn (g_hA)
    factor_mma<<<B * NHEAD * 49, 128>>>(hqkvp, kvTp, hHp, hAp);
    // 7. proj GEMM + bias + residual(x0) -> x1 fp16
    hgemm<1, __half><<<dim3(CDIM / 128, M / 128), 256>>>(
        hAp, hwp + OFF_PROJ, x1p, M, CDIM, CDIM, proj_b, x0p);
    // 8. LN2 -> fp16
    ln_k<<<M, 128>>>(x1p, ln2_w, ln2_b, hAp);
    // 9. fc1 + bias + gelu -> fp16 hidden
    hgemm<2, __half><<<dim3(HID / 128, M / 128), 256>>>(
        hAp, hwp + OFF_FC1, hHp, M, HID, CDIM, fc1_b, nullptr);
    // 10. fc2 + bias + residual(x1) -> out fp32
    hgemm<1, float><<<dim3(CDIM / 128, M / 128), 256>>>(
        hHp, hwp + OFF_FC2, (float*)d_out, M, CDIM, HID, fc2_b, x1p);
}

// round 17
// speedup vs baseline: 1.2695x; 1.1914x over previous
#include <cuda_runtime.h>
#include <cuda_fp16.h>
#include <math.h>
#include <stdint.h>

// ---------------- problem constants (fixed shapes) ----------------
#define NTOK   3136       // 56*56
#define HH     56
#define CDIM   512
#define C3     1536
#define NHEAD  8
#define CH     64
#define HID    2048
#define BMAX   16
#define NCHUNK 7          // kv token chunks (7*448 = 3136)
#define KSCH   32         // kstats chunks (32*98 = 3136)

// packed conv weights: [0,576) w3 pairs, [576,2976) w5, [2976,7680) w7
#define WPK_W5 576
#define WPK_W7 2976
#define WPK_TOT 7680
#define WPK_CPE (WPK_TOT + 9 * 512)        // + cpe transpose
#define WPKT_N  (8 * 49 * 32)              // tap-major tiled layout
#define WPK_ALL (WPK_CPE + WPKT_N)

// ---------------- scratch (device globals; no allocations) --------
__device__ __half  g_x0  [(size_t)BMAX * NTOK * CDIM];
__device__ __half  g_x1  [(size_t)BMAX * NTOK * CDIM];
__device__ __half  g_hA  [(size_t)BMAX * NTOK * CDIM];
__device__ __half  g_hqkv[(size_t)BMAX * NTOK * C3];
__device__ __half  g_hH  [(size_t)BMAX * NTOK * HID];
__device__ __half  g_hw  [1536*512 + 512*512 + 2048*512 + 512*2048];
__device__ __half  g_kvT [BMAX * NHEAD * CH * CH];
__device__ __half2 g_wpk [WPK_TOT];
__device__ __half2 g_wpkT[WPKT_N];
__device__ float   g_cwT [9 * 512];
__device__ float   g_kvpart[NCHUNK * BMAX * NHEAD * CH * CH];
__device__ float   g_kmax[BMAX * CDIM];
__device__ float   g_kscale[BMAX * CDIM];
__device__ float   g_pmax[KSCH * BMAX * CDIM];
__device__ float   g_psum[KSCH * BMAX * CDIM];

#define OFF_QKV  0
#define OFF_PROJ (1536*512)
#define OFF_FC1  (1536*512 + 512*512)
#define OFF_FC2  (1536*512 + 512*512 + 2048*512)

// ---------------- smem helpers -------------------------------------
__device__ __forceinline__ uint32_t smem_u32(const void* p) {
    uint32_t a;
    asm("{ .reg .u64 t; cvta.to.shared.u64 t, %1; cvt.u32.u64 %0, t; }" : "=r"(a) : "l"(p));
    return a;
}
__device__ __forceinline__ uint32_t swz(uint32_t r, uint32_t wp) {
    uint32_t off = r * 64 + wp * 4;
    return off ^ ((off >> 3) & 0x30);
}
__device__ __forceinline__ uint32_t swz128(uint32_t r, uint32_t ch) {
    return (r * 128 + ch * 16) ^ ((r & 7) << 4);
}
__device__ __forceinline__ void cpa16(uint32_t dst, const void* src) {
    asm volatile("cp.async.cg.shared.global [%0], [%1], 16;" :: "r"(dst), "l"(src));
}
#define CP_COMMIT() asm volatile("cp.async.commit_group;" ::: "memory")
#define CP_WAIT1()  asm volatile("cp.async.wait_group 1;" ::: "memory")
#define CP_WAIT0()  asm volatile("cp.async.wait_group 0;" ::: "memory")

__device__ __forceinline__ void ldsm_x4(uint32_t* r, uint32_t addr) {
    asm volatile("ldmatrix.sync.aligned.m8n8.x4.shared.b16 {%0,%1,%2,%3}, [%4];"
        : "=r"(r[0]), "=r"(r[1]), "=r"(r[2]), "=r"(r[3]) : "r"(addr));
}
__device__ __forceinline__ void ldsm_x4_t(uint32_t* r, uint32_t addr) {
    asm volatile("ldmatrix.sync.aligned.m8n8.x4.trans.shared.b16 {%0,%1,%2,%3}, [%4];"
        : "=r"(r[0]), "=r"(r[1]), "=r"(r[2]), "=r"(r[3]) : "r"(addr));
}
__device__ __forceinline__ void mma16816(float* c, const uint32_t* a, const uint32_t* b) {
    asm volatile(
        "mma.sync.aligned.m16n8k16.row.col.f32.f16.f16.f32 "
        "{%0,%1,%2,%3}, {%4,%5,%6,%7}, {%8,%9}, {%0,%1,%2,%3};"
        : "+f"(c[0]), "+f"(c[1]), "+f"(c[2]), "+f"(c[3])
        : "r"(a[0]), "r"(a[1]), "r"(a[2]), "r"(a[3]), "r"(b[0]), "r"(b[1]));
}

// ================= HGEMM: 128x128x32, 3-stage cp.async + ldmatrix ==
// (R14/R9 proven configuration — 256 thr, 64x32 warp tile)
template <int EPI, typename TOUT>
__global__ __launch_bounds__(256, 2) void hgemm(const __half* __restrict__ A,
                                                const __half* __restrict__ Bw,
                                                TOUT* __restrict__ C,
                                                int M, int N, int K,
                                                const float* __restrict__ bias,
                                                const __half* __restrict__ res)
{
    __shared__ __align__(16) char sm[3][16384];
    const uint32_t smb = smem_u32(sm);

    const int tid = threadIdx.x;
    const int m0 = blockIdx.y * 128, n0 = blockIdx.x * 128;
    const int w = tid >> 5, lane = tid & 31;
    const int wm = w & 1, wn = w >> 1;

    const int pr = tid >> 2, pch = tid & 3;
    const __half* Apg = A  + (size_t)(m0 + pr) * K + pch * 8;
    const __half* Bpg = Bw + (size_t)(n0 + pr) * K + pch * 8;
    const uint32_t d0 = swz(pr, pch * 4);
    const uint32_t d1 = swz(pr + 64, pch * 4);
    const int nstage = K >> 5;

    const int arow = wm * 64 + (lane & 15);
    const int achk = lane >> 4;
    const int brow = wn * 32 + (lane & 7) + ((lane >> 4) << 3);
    const int bchk = (lane >> 3) & 1;

    float acc[4][4][4] = {};

#pragma unroll
    for (int s = 0; s < 2; s++) {
        uint32_t sb = smb + s * 16384;
        cpa16(sb + d0,        Apg + s * 32);
        cpa16(sb + d1,        Apg + (size_t)64 * K + s * 32);
        cpa16(sb + 8192 + d0, Bpg + s * 32);
        cpa16(sb + 8192 + d1, Bpg + (size_t)64 * K + s * 32);
        CP_COMMIT();
    }

    for (int s = 0; s < nstage; s++) {
        if (s < nstage - 2) CP_WAIT1(); else CP_WAIT0();
        __syncthreads();

        if (s + 2 < nstage) {
            int st = s + 2;
            uint32_t sb = smb + (st % 3) * 16384;
            cpa16(sb + d0,        Apg + st * 32);
            cpa16(sb + d1,        Apg + (size_t)64 * K + st * 32);
            cpa16(sb + 8192 + d0, Bpg + st * 32);
            cpa16(sb + 8192 + d1, Bpg + (size_t)64 * K + st * 32);
            CP_COMMIT();
        }

        const uint32_t aB = smb + (s % 3) * 16384;
        const uint32_t bB = aB + 8192;
#pragma unroll
        for (int kk = 0; kk < 2; kk++) {
            uint32_t afr[4][4], bfr[4][2];
#pragma unroll
            for (int i = 0; i < 4; i++)
                ldsm_x4(afr[i], aB + swz(arow + i * 16, (kk * 2 + achk) * 4));
#pragma unroll
            for (int jj = 0; jj < 2; jj++) {
                uint32_t r[4];
                ldsm_x4(r, bB + swz(brow + jj * 16, (kk * 2 + bchk) * 4));
                bfr[2 * jj][0] = r[0]; bfr[2 * jj][1] = r[1];
                bfr[2 * jj + 1][0] = r[2]; bfr[2 * jj + 1][1] = r[3];
            }
#pragma unroll
            for (int i = 0; i < 4; i++)
#pragma unroll
                for (int j = 0; j < 4; j++)
                    mma16816(acc[i][j], afr[i], bfr[j]);
        }
    }

    // ---- epilogue ----
    const int g = lane >> 2, tg = lane & 3;
#pragma unroll
    for (int i = 0; i < 4; i++) {
        const int r0 = m0 + wm * 64 + i * 16 + g;
#pragma unroll
        for (int j = 0; j < 4; j++) {
            const int c = n0 + wn * 32 + j * 8 + tg * 2;
            float v0 = acc[i][j][0], v1 = acc[i][j][1];
            float v2 = acc[i][j][2], v3 = acc[i][j][3];
            if (EPI == 1 || EPI == 2) {
                float bb0 = bias[c], bb1 = bias[c + 1];
                v0 += bb0; v1 += bb1; v2 += bb0; v3 += bb1;
            }
            if (EPI == 1) {
                __half2 r_a = *(const __half2*)(res + (size_t)r0 * N + c);
                __half2 r_b = *(const __half2*)(res + (size_t)(r0 + 8) * N + c);
                v0 += __low2float(r_a); v1 += __high2float(r_a);
                v2 += __low2float(r_b); v3 += __high2float(r_b);
                if (sizeof(TOUT) == 4) {
                    float* out = (float*)C;
                    *(float2*)(out + (size_t)r0 * N + c)       = make_float2(v0, v1);
                    *(float2*)(out + (size_t)(r0 + 8) * N + c) = make_float2(v2, v3);
                } else {
                    __half* out = (__half*)C;
                    *(__half2*)(out + (size_t)r0 * N + c)       = __floats2half2_rn(v0, v1);
                    *(__half2*)(out + (size_t)(r0 + 8) * N + c) = __floats2half2_rn(v2, v3);
                }
            } else if (EPI == 2) {
                v0 = 0.5f * v0 * (1.0f + erff(v0 * 0.70710678118654752f));
                v1 = 0.5f * v1 * (1.0f + erff(v1 * 0.70710678118654752f));
                v2 = 0.5f * v2 * (1.0f + erff(v2 * 0.70710678118654752f));
                v3 = 0.5f * v3 * (1.0f + erff(v3 * 0.70710678118654752f));
                __half* out = (__half*)C;
                *(__half2*)(out + (size_t)r0 * N + c)       = __floats2half2_rn(v0, v1);
                *(__half2*)(out + (size_t)(r0 + 8) * N + c) = __floats2half2_rn(v2, v3);
            } else {
                __half* out = (__half*)C;
                *(__half2*)(out + (size_t)r0 * N + c)       = __floats2half2_rn(v0, v1);
                *(__half2*)(out + (size_t)(r0 + 8) * N + c) = __floats2half2_rn(v2, v3);
            }
        }
    }
}

// -------- merged weight transpose+convert (all 4 matrices) ---------
__global__ __launch_bounds__(256) void wconv_all(const float* __restrict__ qkv_w,
                                                 const float* __restrict__ proj_w,
                                                 const float* __restrict__ fc1_w,
                                                 const float* __restrict__ fc2_w,
                                                 __half* __restrict__ hw)
{
    __shared__ float t[32][33];
    int bid = blockIdx.x;
    const float* in; __half* out; int K, N, tk, tn;
    if (bid < 768)       { in = qkv_w;  out = hw + OFF_QKV;  K = 512;  N = 1536; int r = bid;        tk = r & 15; tn = r >> 4; }
    else if (bid < 1024) { in = proj_w; out = hw + OFF_PROJ; K = 512;  N = 512;  int r = bid - 768;  tk = r & 15; tn = r >> 4; }
    else if (bid < 2048) { in = fc1_w;  out = hw + OFF_FC1;  K = 512;  N = 2048; int r = bid - 1024; tk = r & 15; tn = r >> 4; }
    else                 { in = fc2_w;  out = hw + OFF_FC2;  K = 2048; N = 512;  int r = bid - 2048; tk = r & 63; tn = r >> 6; }
    int k0 = tk * 32, n0 = tn * 32;
    int tx = threadIdx.x & 31, ty = threadIdx.x >> 5;
#pragma unroll
    for (int i = 0; i < 32; i += 8)
        t[ty + i][tx] = in[(size_t)(k0 + ty + i) * N + n0 + tx];
    __syncthreads();
#pragma unroll
    for (int i = 0; i < 32; i += 8)
        out[(size_t)(n0 + ty + i) * K + k0 + tx] = __float2half(t[tx][ty + i]);
}

// -------- pack conv weights (pair-major + tap-major) + cpe transpose
__global__ void wpack(const float* __restrict__ w3, const float* __restrict__ w5,
                      const float* __restrict__ w7, const float* __restrict__ cw,
                      __half2* __restrict__ wp, __half2* __restrict__ wpT,
                      float* __restrict__ cwT)
{
    int idx = blockIdx.x * blockDim.x + threadIdx.x;
    if (idx >= WPK_ALL) return;
    if (idx >= WPK_CPE) {
        // tap-major tiled layout: [group g][tap t][pair-in-group pr]
        int j = idx - WPK_CPE;
        int g = j / (49 * 32);
        int rem = j % (49 * 32);
        int t = rem >> 5, pr = rem & 31;
        int pc = g * 32 + pr;
        float v0 = 0.0f, v1 = 0.0f;
        if (pc < 64) {
            if (t < 9)  { v0 = w3[(2 * pc) * 9 + t];          v1 = w3[(2 * pc + 1) * 9 + t]; }
        } else if (pc < 160) {
            int p = pc - 64;
            if (t < 25) { v0 = w5[(2 * p) * 25 + t];          v1 = w5[(2 * p + 1) * 25 + t]; }
        } else {
            int p = pc - 160;
            if (t < 49) { v0 = w7[(2 * p) * 49 + t];          v1 = w7[(2 * p + 1) * 49 + t]; }
        }
        wpT[j] = __floats2half2_rn(v0, v1);
        return;
    }
    if (idx >= WPK_TOT) {
        int j = idx - WPK_TOT;
        int t = j >> 9, c = j & 511;
        cwT[t * 512 + c] = cw[c * 9 + t];
        return;
    }
    const float* src; int p, t, KK;
    if (idx < WPK_W5)      { src = w3; int r = idx;           KK = 9;  p = r / 9;  t = r % 9;  }
    else if (idx < WPK_W7) { src = w5; int r = idx - WPK_W5;  KK = 25; p = r / 25; t = r % 25; }
    else                   { src = w7; int r = idx - WPK_W7;  KK = 49; p = r / 49; t = r % 49; }
    wp[idx] = __floats2half2_rn(src[(2 * p) * KK + t], src[(2 * p + 1) * KK + t]);
}

// ---------------- fused CPE (dw3x3 + residual) + LN1 ---------------
__global__ __launch_bounds__(128) void cpe_ln_k(const float* __restrict__ x,
                                                const float* __restrict__ cwT,
                                                const float* __restrict__ cb,
                                                const float* __restrict__ lw,
                                                const float* __restrict__ lb,
                                                __half* __restrict__ x0,
                                                __half* __restrict__ hA)
{
    int bn = blockIdx.x;
    int n = bn % NTOK;
    int bbase = bn - n;
    int yy = n / HH, xx = n - yy * HH;
    int tid = threadIdx.x;

    float s[4], outv[4];
#pragma unroll
    for (int u = 0; u < 4; u++) s[u] = cb[tid + u * 128];

#pragma unroll
    for (int ky = 0; ky < 3; ky++) {
        int iy = yy + ky - 1;
        if ((unsigned)iy >= (unsigned)HH) continue;
#pragma unroll
        for (int kx = 0; kx < 3; kx++) {
            int ix = xx + kx - 1;
            if ((unsigned)ix >= (unsigned)HH) continue;
            const float* xp = x + (size_t)(bbase + iy * HH + ix) * CDIM;
            const float* wt = cwT + (ky * 3 + kx) * 512;
#pragma unroll
            for (int u = 0; u < 4; u++) {
                int c = tid + u * 128;
                s[u] += __ldg(wt + c) * xp[c];
            }
        }
    }

    const float* xc = x + (size_t)bn * CDIM;
    float lsum = 0.0f;
#pragma unroll
    for (int u = 0; u < 4; u++) {
        int c = tid + u * 128;
        outv[u] = s[u] + xc[c];
        x0[(size_t)bn * CDIM + c] = __float2half(outv[u]);
        lsum += outv[u];
    }

    __shared__ float red[4];
    int lane = tid & 31, wid = tid >> 5;
#pragma unroll
    for (int o = 16; o > 0; o >>= 1) lsum += __shfl_xor_sync(0xffffffffu, lsum, o);
    if (lane == 0) red[wid] = lsum;
    __syncthreads();
    float mean = (red[0] + red[1] + red[2] + red[3]) * (1.0f / CDIM);
    __syncthreads();

    float q = 0.0f;
#pragma unroll
    for (int u = 0; u < 4; u++) { float d = outv[u] - mean; q += d * d; }
#pragma unroll
    for (int o = 16; o > 0; o >>= 1) q += __shfl_xor_sync(0xffffffffu, q, o);
    if (lane == 0) red[wid] = q;
    __syncthreads();
    float var = (red[0] + red[1] + red[2] + red[3]) * (1.0f / CDIM);
    float rstd = rsqrtf(var + 1e-6f);

#pragma unroll
    for (int u = 0; u < 4; u++) {
        int c = tid + u * 128;
        float v = (outv[u] - mean) * rstd * lw[c] + lb[c];
        hA[(size_t)bn * CDIM + c] = __float2half(v);
    }
}

// ---------------- LayerNorm over C=512 (fp16 in) -> fp16 out -------
__global__ __launch_bounds__(128) void ln_k(const __half* __restrict__ x,
                                            const float* __restrict__ w,
                                            const float* __restrict__ b,
                                            __half* __restrict__ y)
{
    int row = blockIdx.x;
    int tid = threadIdx.x;
    uint2 raw = *(const uint2*)(x + (size_t)row * CDIM + tid * 4);
    __half2 h0 = ((const __half2*)&raw)[0];
    __half2 h1 = ((const __half2*)&raw)[1];
    float4 v = make_float4(__low2float(h0), __high2float(h0),
                           __low2float(h1), __high2float(h1));
    __shared__ float red[4];
    int lane = tid & 31, wid = tid >> 5;

    float s = v.x + v.y + v.z + v.w;
#pragma unroll
    for (int o = 16; o > 0; o >>= 1) s += __shfl_xor_sync(0xffffffffu, s, o);
    if (lane == 0) red[wid] = s;
    __syncthreads();
    float mean = (red[0] + red[1] + red[2] + red[3]) * (1.0f / CDIM);
    __syncthreads();

    float4 d = make_float4(v.x - mean, v.y - mean, v.z - mean, v.w - mean);
    float q = d.x * d.x + d.y * d.y + d.z * d.z + d.w * d.w;
#pragma unroll
    for (int o = 16; o > 0; o >>= 1) q += __shfl_xor_sync(0xffffffffu, q, o);
    if (lane == 0) red[wid] = q;
    __syncthreads();
    float var = (red[0] + red[1] + red[2] + red[3]) * (1.0f / CDIM);
    float rstd = rsqrtf(var + 1e-6f);

    float4 wv = ((const float4*)w)[tid];
    float4 bv = ((const float4*)b)[tid];
    float ox = d.x * rstd * wv.x + bv.x;
    float oy = d.y * rstd * wv.y + bv.y;
    float oz = d.z * rstd * wv.z + bv.z;
    float ow = d.w * rstd * wv.w + bv.w;
    uint2 pack;
    ((__half2*)&pack)[0] = __floats2half2_rn(ox, oy);
    ((__half2*)&pack)[1] = __floats2half2_rn(oz, ow);
    *(uint2*)(y + (size_t)row * CDIM + tid * 4) = pack;
}

// ---------------- k-softmax statistics (32 chunks of 98 tokens) ----
__global__ __launch_bounds__(128) void kstats_part(const __half* __restrict__ qkv,
                                                   float* __restrict__ pmax,
                                                   float* __restrict__ psum, int B)
{
    int blk = blockIdx.x;
    int chunk = blk & 31;
    int hcg = (blk >> 5) & 3;
    int b = blk >> 7;
    int hc = hcg * 128 + threadIdx.x;
    const __half* kp = qkv + (size_t)b * NTOK * C3 + CDIM + hc;
    float m = -1e30f, s = 0.0f;
    int n0 = chunk * (NTOK / KSCH);
    for (int n = n0; n < n0 + NTOK / KSCH; n++) {
        float kx = __half2float(kp[(size_t)n * C3]);
        if (kx <= m) s += __expf(kx - m);
        else { s = s * __expf(m - kx) + 1.0f; m = kx; }
    }
    int BC = B * CDIM;
    pmax[chunk * BC + b * CDIM + hc] = m;
    psum[chunk * BC + b * CDIM + hc] = s;
}

__global__ void kstats_comb(const float* __restrict__ pmax, const float* __restrict__ psum,
                            float* __restrict__ kmax, float* __restrict__ kscale, int B)
{
    int idx = blockIdx.x * blockDim.x + threadIdx.x;
    int BC = B * CDIM;
    if (idx >= BC) return;
    float m = -1e30f, s = 0.0f;
#pragma unroll
    for (int c = 0; c < KSCH; c++) {
        float pm = pmax[c * BC + idx];
        float ps = psum[c * BC + idx];
        if (pm <= m) s += ps * __expf(pm - m);
        else { s = s * __expf(m - pm) + ps; m = pm; }
    }
    kmax[idx] = m;
    kscale[idx] = 1.0f / s;
}

// ---------------- kv partial via MMA: kvpart = E^T V ---------------
__global__ __launch_bounds__(128) void kvp_mma(const __half* __restrict__ qkv,
                                               const float* __restrict__ kmax,
                                               float* __restrict__ kvpart)
{
    __shared__ __align__(16) __half Es[64 * 64];
    __shared__ __align__(16) __half Vs[64 * 64];
    __shared__ float km[64];
    const uint32_t Eb = smem_u32(Es), Vb = smem_u32(Vs);

    int chunk = blockIdx.x % NCHUNK;
    int bh = blockIdx.x / NCHUNK;
    int b = bh >> 3, h = bh & 7;
    int tid = threadIdx.x, w = tid >> 5, lane = tid & 31;
    if (tid < 64) km[tid] = kmax[b * CDIM + h * CH + tid];
    __syncthreads();

    float acc[8][4] = {};
    const __half* base = qkv + (size_t)(b * NTOK + chunk * 448) * C3 + h * CH;

    const int pr = tid >> 1;
    const int pc0 = (tid & 1) * 4;

    for (int t0 = 0; t0 < 448; t0 += 64) {
        {
            const __half* vg = base + (size_t)(t0 + pr) * C3 + 2 * CDIM;
#pragma unroll
            for (int c = 0; c < 4; c++)
                cpa16(Vb + swz128(pr, pc0 + c), vg + (pc0 + c) * 8);
            CP_COMMIT();
        }
        {
            const __half* kg = base + (size_t)(t0 + pr) * C3 + CDIM;
#pragma unroll
            for (int c = 0; c < 4; c++) {
                uint4 raw = *(const uint4*)(kg + (pc0 + c) * 8);
                __half2* hp = (__half2*)&raw;
                uint4 outv;
                __half2* op = (__half2*)&outv;
#pragma unroll
                for (int t = 0; t < 4; t++) {
                    int cc = (pc0 + c) * 8 + t * 2;
                    float e0 = __expf(__low2float(hp[t])  - km[cc]);
                    float e1 = __expf(__high2float(hp[t]) - km[cc + 1]);
                    op[t] = __floats2half2_rn(e0, e1);
                }
                *(uint4*)((char*)Es + swz128(pr, pc0 + c)) = outv;
            }
        }
        CP_WAIT0();
        __syncthreads();

#pragma unroll
        for (int ts = 0; ts < 4; ts++) {
            int tb = ts * 16;
            uint32_t ar[4], afr[4];
            ldsm_x4_t(ar, Eb + swz128(tb + (lane & 15), 2 * w + (lane >> 4)));
            afr[0] = ar[0]; afr[1] = ar[2]; afr[2] = ar[1]; afr[3] = ar[3];

            uint32_t bfr[8][2];
#pragma unroll
            for (int p = 0; p < 4; p++) {
                uint32_t rr[4];
                ldsm_x4_t(rr, Vb + swz128(tb + (lane & 7) + (((lane >> 3) & 1) << 3),
                                          2 * p + (lane >> 4)));
                bfr[2 * p][0] = rr[0];     bfr[2 * p][1] = rr[1];
                bfr[2 * p + 1][0] = rr[2]; bfr[2 * p + 1][1] = rr[3];
            }
#pragma unroll
            for (int j = 0; j < 8; j++)
                mma16816(acc[j], afr, bfr[j]);
        }
        __syncthreads();
    }

    const int g = lane >> 2, tg = lane & 3;
    float* outp = kvpart + ((size_t)chunk * BMAX * NHEAD + bh) * 4096;
    const int r0 = 16 * w + g;
#pragma unroll
    for (int j = 0; j < 8; j++) {
        int c = j * 8 + tg * 2;
        *(float2*)(outp + r0 * 64 + c)       = make_float2(acc[j][0], acc[j][1]);
        *(float2*)(outp + (r0 + 8) * 64 + c) = make_float2(acc[j][2], acc[j][3]);
    }
}

// kv combine: apply 1/sum scale, emit fp16 kvT[v][k]
__global__ void kvcomb(const float* __restrict__ kvpart, const float* __restrict__ kscale,
                       __half* __restrict__ kvT, int B)
{
    int idx = blockIdx.x * blockDim.x + threadIdx.x;
    if (idx >= B * NHEAD * 4096) return;
    int bh = idx >> 12, e = idx & 4095;
    int k = e >> 6, v = e & 63;
    int b = bh >> 3, h = bh & 7;
    float s = 0.0f;
#pragma unroll
    for (int c = 0; c < NCHUNK; c++)
        s += kvpart[((size_t)c * BMAX * NHEAD + bh) * 4096 + e];
    s *= kscale[b * CDIM + h * CH + k];
    kvT[(size_t)bh * 4096 + v * 64 + k] = __float2half(s);
}

// ---------------- crpe: spatial smem-tiled depthwise conv ----------
// grid: (group 0..7, tile 0..48, batch); 256 threads
// block covers 8x8 spatial x 64 channels (32 pairs)
__global__ __launch_bounds__(256) void crpe_tile(const __half* __restrict__ qkv,
                                                 const __half2* __restrict__ wpT,
                                                 const float* __restrict__ b3,
                                                 const float* __restrict__ b5,
                                                 const float* __restrict__ b7,
                                                 __half* __restrict__ attn)
{
    __shared__ __align__(16) __half2 vs[196 * 32];   // [row][pair], 128B rows

    const int g = blockIdx.x, tile = blockIdx.y, b = blockIdx.z;
    int K, P;
    if (g < 2)      { K = 3; P = 1; }
    else if (g < 5) { K = 5; P = 2; }
    else            { K = 7; P = 3; }
    const int ext = 8 + 2 * P;
    const int ty0 = (tile / 7) * 8, tx0 = (tile % 7) * 8;

    const int tid = threadIdx.x;
    const int lane = tid & 31;        // pair within group
    const int wg = tid >> 5;          // spatial column 0..7

    // ---- stage v patch (64 ch) into smem, zero halo outside image ----
    const uint32_t vsb = smem_u32(vs);
    const __half* vbase = qkv + 2 * CDIM + g * 64;
    const int nchunk = ext * ext * 8;          // 16B chunks
    for (int c = tid; c < nchunk; c += 256) {
        int row = c >> 3, ch = c & 7;
        int sy = row / ext, sx = row - sy * ext;
        int gy = ty0 - P + sy, gx = tx0 - P + sx;
        uint32_t dst = vsb + row * 128 + ch * 16;
        if ((unsigned)gy < (unsigned)HH && (unsigned)gx < (unsigned)HH) {
            cpa16(dst, vbase + (size_t)(b * NTOK + gy * HH + gx) * C3 + ch * 8);
        } else {
            uint4 z = make_uint4(0, 0, 0, 0);
            *(uint4*)((char*)vs + row * 128 + ch * 16) = z;
        }
    }
    CP_COMMIT();
    CP_WAIT0();
    __syncthreads();

    // ---- bias ----
    const int pc = g * 32 + lane;
    const int hc = pc * 2;
    float bb0, bb1;
    if (pc < 64)       { bb0 = b3[hc];       bb1 = b3[hc + 1]; }
    else if (pc < 160) { bb0 = b5[hc - 128]; bb1 = b5[hc - 127]; }
    else               { bb0 = b7[hc - 320]; bb1 = b7[hc - 319]; }
    __half2 bias2 = __floats2half2_rn(bb0, bb1);

    __half2 acc[8];
#pragma unroll
    for (int j = 0; j < 8; j++) acc[j] = bias2;

    // ---- taps: weight shared across 8 positions per thread ----
    const __half2* wt = wpT + (g * 49) * 32 + lane;
    for (int t = 0; t < K * K; t++) {
        int dy = t / K, dx = t - dy * K;
        __half2 wv = __ldg(wt + t * 32);
        int rbase = dy * ext + wg + dx;
#pragma unroll
        for (int j = 0; j < 8; j++)
            acc[j] = __hfma2(vs[(rbase + j * ext) * 32 + lane], wv, acc[j]);
    }

    // ---- epilogue: multiply by q, store ----
#pragma unroll
    for (int j = 0; j < 8; j++) {
        int gy = ty0 + j, gx = tx0 + wg;
        size_t bn = (size_t)b * NTOK + gy * HH + gx;
        __half2 q2 = *(const __half2*)(qkv + bn * C3 + hc);
        *(__half2*)(attn + bn * CDIM + hc) = __hmul2(q2, acc[j]);
    }
}

// ---------------- factor att via MMA: hout = crpe + 0.125 q@kv -----
__global__ __launch_bounds__(128) void factor_mma(const __half* __restrict__ qkv,
                                                  const __half* __restrict__ kvT,
                                                  const __half* __restrict__ crpe,
                                                  __half* __restrict__ hout)
{
    __shared__ __align__(16) __half qs[64 * 64];
    __shared__ __align__(16) __half bs[64 * 64];
    const uint32_t qb = smem_u32(qs), bb = smem_u32(bs);

    int t = blockIdx.x;
    int tile = t % 49, bh = t / 49;
    int b = bh >> 3, h = bh & 7;
    int n0 = tile * 64;
    int tid = threadIdx.x, w = tid >> 5, lane = tid & 31;

    {
        int r = tid >> 1;
        int c0 = (tid & 1) * 4;
        const __half* qg = qkv + (size_t)(b * NTOK + n0 + r) * C3 + h * CH;
        const __half* kg = kvT + (size_t)bh * 4096 + r * 64;
#pragma unroll
        for (int c = 0; c < 4; c++) {
            cpa16(qb + swz128(r, c0 + c), qg + (c0 + c) * 8);
            cpa16(bb + swz128(r, c0 + c), kg + (c0 + c) * 8);
        }
        CP_COMMIT();
        CP_WAIT0();
    }
    __syncthreads();

    const int arow = w * 16 + (lane & 15);
    const int achk = lane >> 4;
    const int brow = (lane & 7) + ((lane >> 4) << 3);
    const int bchk = (lane >> 3) & 1;

    float acc[8][4] = {};
#pragma unroll
    for (int kk = 0; kk < 4; kk++) {
        uint32_t afr[4], bfr[8][2];
        ldsm_x4(afr, qb + swz128(arow, kk * 2 + achk));
#pragma unroll
        for (int jj = 0; jj < 4; jj++) {
            uint32_t rr[4];
            ldsm_x4(rr, bb + swz128(jj * 16 + brow, kk * 2 + bchk));
            bfr[2 * jj][0] = rr[0]; bfr[2 * jj][1] = rr[1];
            bfr[2 * jj + 1][0] = rr[2]; bfr[2 * jj + 1][1] = rr[3];
        }
#pragma unroll
        for (int j = 0; j < 8; j++)
            mma16816(acc[j], afr, bfr[j]);
    }

    const int g = lane >> 2, tg = lane & 3;
    const int row = n0 + w * 16 + g;
#pragma unroll
    for (int j = 0; j < 8; j++) {
        int c = j * 8 + tg * 2;
        size_t o0 = (size_t)(b * NTOK + row) * CDIM + h * CH + c;
        size_t o1 = o0 + (size_t)8 * CDIM;
        __half2 cr0 = *(const __half2*)(crpe + o0);
        __half2 cr1 = *(const __half2*)(crpe + o1);
        float v0 = __low2float(cr0)  + 0.125f * acc[j][0];
        float v1 = __high2float(cr0) + 0.125f * acc[j][1];
        float v2 = __low2float(cr1)  + 0.125f * acc[j][2];
        float v3 = __high2float(cr1) + 0.125f * acc[j][3];
        *(__half2*)(hout + o0) = __floats2half2_rn(v0, v1);
        *(__half2*)(hout + o1) = __floats2half2_rn(v2, v3);
    }
}

// ---------------- launch ------------------------------------------
extern "C" void kernel_launch(void* const* d_in, const int* in_sizes, int n_in,
                              void* d_out, int out_size)
{
    const float* x      = (const float*)d_in[0];
    const float* cpe_w  = (const float*)d_in[3];
    const float* cpe_b  = (const float*)d_in[4];
    const float* ln1_w  = (const float*)d_in[5];
    const float* ln1_b  = (const float*)d_in[6];
    const float* qkv_w  = (const float*)d_in[7];
    const float* proj_w = (const float*)d_in[8];
    const float* proj_b = (const float*)d_in[9];
    const float* w3     = (const float*)d_in[10];
    const float* b3     = (const float*)d_in[11];
    const float* w5     = (const float*)d_in[12];
    const float* b5     = (const float*)d_in[13];
    const float* w7     = (const float*)d_in[14];
    const float* b7     = (const float*)d_in[15];
    const float* ln2_w  = (const float*)d_in[16];
    const float* ln2_b  = (const float*)d_in[17];
    const float* fc1_w  = (const float*)d_in[18];
    const float* fc1_b  = (const float*)d_in[19];
    const float* fc2_w  = (const float*)d_in[20];
    const float* fc2_b  = (const float*)d_in[21];

    const int B = in_sizes[0] / (NTOK * CDIM);
    const int M = B * NTOK;

    float *kvpartp, *kmaxp, *kscalep, *pmaxp, *psump, *cwTp;
    __half *x0p, *x1p, *hAp, *hqkvp, *hHp, *hwp, *kvTp;
    __half2 *wpkp, *wpkTp;
    cudaGetSymbolAddress((void**)&x0p, g_x0);
    cudaGetSymbolAddress((void**)&x1p, g_x1);
    cudaGetSymbolAddress((void**)&kvTp, g_kvT);
    cudaGetSymbolAddress((void**)&wpkp, g_wpk);
    cudaGetSymbolAddress((void**)&wpkTp, g_wpkT);
    cudaGetSymbolAddress((void**)&cwTp, g_cwT);
    cudaGetSymbolAddress((void**)&kvpartp, g_kvpart);
    cudaGetSymbolAddress((void**)&kmaxp, g_kmax);
    cudaGetSymbolAddress((void**)&kscalep, g_kscale);
    cudaGetSymbolAddress((void**)&pmaxp, g_pmax);
    cudaGetSymbolAddress((void**)&psump, g_psum);
    cudaGetSymbolAddress((void**)&hAp, g_hA);
    cudaGetSymbolAddress((void**)&hqkvp, g_hqkv);
    cudaGetSymbolAddress((void**)&hHp, g_hH);
    cudaGetSymbolAddress((void**)&hwp, g_hw);

    // second stream + events (host objects only; same graph every call)
    cudaStream_t s1;
    cudaStreamCreateWithFlags(&s1, cudaStreamNonBlocking);
    cudaEvent_t eFork0, eW, eQ, eK;
    cudaEventCreateWithFlags(&eFork0, cudaEventDisableTiming);
    cudaEventCreateWithFlags(&eW,     cudaEventDisableTiming);
    cudaEventCreateWithFlags(&eQ,     cudaEventDisableTiming);
    cudaEventCreateWithFlags(&eK,     cudaEventDisableTiming);

    // 0. weight packing on stream 0 (cpe_ln + crpe depend on it in-order)
    wpack<<<(WPK_ALL + 255) / 256, 256>>>(w3, w5, w7, cpe_w, wpkp, wpkTp, cwTp);

    // ---- fork: big weight transpose on s1 concurrent with CPE+LN1 ----
    cudaEventRecord(eFork0, 0);
    cudaStreamWaitEvent(s1, eFork0, 0);

    wconv_all<<<3072, 256, 0, s1>>>(qkv_w, proj_w, fc1_w, fc2_w, hwp);
    cpe_ln_k<<<M, 128>>>(x, cwTp, cpe_b, ln1_w, ln1_b, x0p, hAp);

    cudaEventRecord(eW, s1);
    cudaStreamWaitEvent(0, eW, 0);     // qkv GEMM needs weights

    // 2. qkv GEMM -> fp16 [M,1536]
    hgemm<3, __half><<<dim3(C3 / 128, M / 128), 256>>>(
        hAp, hwp + OFF_QKV, hqkvp, M, C3, CDIM, nullptr, nullptr);

    // ---- fork: kstats+kv chain on s1 concurrent with crpe on s0 ----
    cudaEventRecord(eQ, 0);
    cudaStreamWaitEvent(s1, eQ, 0);

    kstats_part<<<B * 128, 128, 0, s1>>>(hqkvp, pmaxp, psump, B);
    kstats_comb<<<(B * CDIM + 255) / 256, 256, 0, s1>>>(pmaxp, psump, kmaxp, kscalep, B);
    kvp_mma<<<B * NHEAD * NCHUNK, 128, 0, s1>>>(hqkvp, kmaxp, kvpartp);
    kvcomb<<<(B * NHEAD * 4096 + 255) / 256, 256, 0, s1>>>(kvpartp, kscalep, kvTp, B);

    // 5. crpe (spatial smem-tiled) -> fp16 tmp (g_hH)
    crpe_tile<<<dim3(8, 49, B), 256>>>(hqkvp, wpkTp, b3, b5, b7, hHp);

    cudaEventRecord(eK, s1);
    cudaStreamWaitEvent(0, eK, 0);     // factor needs kvT

    // 6. factor attention via MMA -> fp16 attn (g_hA)
    factor_mma<<<B * NHEAD * 49, 128>>>(hqkvp, kvTp, hHp, hAp);
    // 7. proj GEMM + bias + residual(x0) -> x1 fp16
    hgemm<1, __half><<<dim3(CDIM / 128, M / 128), 256>>>(
        hAp, hwp + OFF_PROJ, x1p, M, CDIM, CDIM, proj_b, x0p);
    // 8. LN2 -> fp16
    ln_k<<<M, 128>>>(x1p, ln2_w, ln2_b, hAp);
    // 9. fc1 + bias + gelu -> fp16 hidden
    hgemm<2, __half><<<dim3(HID / 128, M / 128), 256>>>(
        hAp, hwp + OFF_FC1, hHp, M, HID, CDIM, fc1_b, nullptr);
    // 10. fc2 + bias + residual(x1) -> out fp32
    hgemm<1, float><<<dim3(CDIM / 128, M / 128), 256>>>(
        hHp, hwp + OFF_FC2, (float*)d_out, M, CDIM, HID, fc2_b, x1p);
}